// round 1
// baseline (speedup 1.0000x reference)
#include <cuda_runtime.h>
#include <cuda_bf16.h>

#define N_NODES 50000
#define N_EDGES 800000
#define N_GRAPHS 64
#define CH 64

// ---------------- scratch (static device globals; no allocation) ----------------
__device__ float g_T[N_NODES * CH];      // gemm output (h = x @ W)
__device__ float g_S[N_NODES * CH];      // skip gemm output (x @ We)
__device__ float g_H[N_NODES * CH];      // stack-1 state
__device__ float g_HS[N_NODES * CH];     // stack-2 state
__device__ float g_dinv[N_NODES];
__device__ int   g_cnt[N_NODES];
__device__ int   g_off[N_NODES + 1];
__device__ int   g_cursor[N_NODES];
__device__ int   g_csrsrc[N_EDGES];
__device__ float g_csrnorm[N_EDGES];
__device__ float g_psum[N_GRAPHS * CH];
__device__ float g_pcnt[N_GRAPHS];

// ---------------- zero scratch ----------------
__global__ void zero_kernel() {
    int i = blockIdx.x * blockDim.x + threadIdx.x;
    if (i < N_NODES) g_cnt[i] = 0;
    if (i < N_GRAPHS * CH) g_psum[i] = 0.f;
    if (i < N_GRAPHS) g_pcnt[i] = 0.f;
}

// ---------------- degree histogram (int atomics, random -> low contention) ----------------
__global__ void hist_kernel(const int* __restrict__ dst) {
    int e = blockIdx.x * blockDim.x + threadIdx.x;
    if (e < N_EDGES) atomicAdd(&g_cnt[dst[e]], 1);
}

// ---------------- single-block exclusive scan + dinv ----------------
__global__ void scan_kernel() {
    __shared__ int part[1024];
    const int CHUNK = 49;  // 1024*49 = 50176 >= 50000
    int tid = threadIdx.x;
    int base = tid * CHUNK;
    int end = min(base + CHUNK, N_NODES);
    int sum = 0;
    for (int j = base; j < end; j++) sum += g_cnt[j];
    part[tid] = sum;
    __syncthreads();
    for (int d = 1; d < 1024; d <<= 1) {
        int v = (tid >= d) ? part[tid - d] : 0;
        __syncthreads();
        part[tid] += v;
        __syncthreads();
    }
    int run = part[tid] - sum;  // exclusive prefix
    for (int j = base; j < end; j++) {
        g_off[j] = run;
        g_cursor[j] = run;
        int c = g_cnt[j];
        g_dinv[j] = rsqrtf(1.0f + (float)c);   // deg = 1 (self-loop) + in-degree
        run += c;
    }
    if (tid == 0) g_off[N_NODES] = N_EDGES;
}

// ---------------- CSR fill (atomic ticket; order inside bucket irrelevant) ----------------
__global__ void fill_kernel(const int* __restrict__ src, const int* __restrict__ dst) {
    int e = blockIdx.x * blockDim.x + threadIdx.x;
    if (e < N_EDGES) {
        int s = src[e], d = dst[e];
        int slot = atomicAdd(&g_cursor[d], 1);
        g_csrsrc[slot] = s;
        g_csrnorm[slot] = g_dinv[s] * g_dinv[d];
    }
}

// ---------------- GEMM: Y[n,64] = X[n,64] @ W[64,64], R8xC8 register tile ----------------
// block: 128 threads, 128 rows/block. smem: W (16KB) + X^T (32KB) = 48KB.
__global__ void __launch_bounds__(128) gemm64_kernel(const float* __restrict__ X,
                                                     const float* __restrict__ W,
                                                     float* __restrict__ Y, int nrows) {
    __shared__ float sW[64 * 64];    // [k][c]
    __shared__ float sX[64 * 128];   // [k][r] (transposed tile)
    int tid = threadIdx.x;
    int rowBase = blockIdx.x * 128;

    // load W (row-major, same layout)
#pragma unroll
    for (int i = 0; i < 32; i++) sW[tid + i * 128] = W[tid + i * 128];

    // load X tile transposed: 2048 float4 / 128 threads = 16 each
#pragma unroll
    for (int j = 0; j < 16; j++) {
        int idx4 = tid + j * 128;      // 0..2047
        int r = idx4 >> 4;             // tile row
        int kq = idx4 & 15;            // float4 index within row
        int grow = rowBase + r;
        float4 v = (grow < nrows) ? ((const float4*)X)[grow * 16 + kq]
                                  : make_float4(0.f, 0.f, 0.f, 0.f);
        sX[(kq * 4 + 0) * 128 + r] = v.x;
        sX[(kq * 4 + 1) * 128 + r] = v.y;
        sX[(kq * 4 + 2) * 128 + r] = v.z;
        sX[(kq * 4 + 3) * 128 + r] = v.w;
    }
    __syncthreads();

    int tx = tid & 7, ty = tid >> 3;
    int c0 = tx * 8, r0 = ty * 8;
    float acc[8][8];
#pragma unroll
    for (int i = 0; i < 8; i++)
#pragma unroll
        for (int j = 0; j < 8; j++) acc[i][j] = 0.f;

#pragma unroll 8
    for (int k = 0; k < 64; k++) {
        float4 w0 = *(const float4*)&sW[k * 64 + c0];
        float4 w1 = *(const float4*)&sW[k * 64 + c0 + 4];
        float4 x0 = *(const float4*)&sX[k * 128 + r0];
        float4 x1 = *(const float4*)&sX[k * 128 + r0 + 4];
        float xs[8] = {x0.x, x0.y, x0.z, x0.w, x1.x, x1.y, x1.z, x1.w};
        float ws[8] = {w0.x, w0.y, w0.z, w0.w, w1.x, w1.y, w1.z, w1.w};
#pragma unroll
        for (int ri = 0; ri < 8; ri++)
#pragma unroll
            for (int ci = 0; ci < 8; ci++) acc[ri][ci] += xs[ri] * ws[ci];
    }

#pragma unroll
    for (int ri = 0; ri < 8; ri++) {
        int row = rowBase + r0 + ri;
        if (row < nrows) {
            float4 o0 = make_float4(acc[ri][0], acc[ri][1], acc[ri][2], acc[ri][3]);
            float4 o1 = make_float4(acc[ri][4], acc[ri][5], acc[ri][6], acc[ri][7]);
            ((float4*)Y)[row * 16 + (c0 >> 2)] = o0;
            ((float4*)Y)[row * 16 + (c0 >> 2) + 1] = o1;
        }
    }
}

// ---------------- propagation (gather CSR) + GCN combine + residual/skip ----------------
// warp per node; lane handles channels lane, lane+32.
// relu_add=1: Hout = relu(gcn) + relu(add_in + add_bias)   (layer-1 skip MLP)
// relu_add=0: Hout = relu(gcn) + add_in                    (layer-2 residual)
__global__ void prop_kernel(const float* __restrict__ T, const float* __restrict__ bias,
                            const float* __restrict__ add_in, const float* __restrict__ add_bias,
                            float* __restrict__ Hout, int relu_add) {
    int warp = (blockIdx.x * blockDim.x + threadIdx.x) >> 5;
    int lane = threadIdx.x & 31;
    if (warp >= N_NODES) return;
    int i = warp;
    int s0 = g_off[i], s1 = g_off[i + 1];
    float a0 = 0.f, a1 = 0.f;
    for (int s = s0; s < s1; s++) {
        int src = g_csrsrc[s];
        float nm = g_csrnorm[s];
        a0 += nm * T[src * CH + lane];
        a1 += nm * T[src * CH + 32 + lane];
    }
    float dv = g_dinv[i];
    float sn = dv * dv;
    float g0 = fmaxf(a0 + sn * T[i * CH + lane] + bias[lane], 0.f);
    float g1 = fmaxf(a1 + sn * T[i * CH + 32 + lane] + bias[32 + lane], 0.f);
    float ad0, ad1;
    if (relu_add) {
        ad0 = fmaxf(add_in[i * CH + lane] + add_bias[lane], 0.f);
        ad1 = fmaxf(add_in[i * CH + 32 + lane] + add_bias[32 + lane], 0.f);
    } else {
        ad0 = add_in[i * CH + lane];
        ad1 = add_in[i * CH + 32 + lane];
    }
    Hout[i * CH + lane] = g0 + ad0;
    Hout[i * CH + 32 + lane] = g1 + ad1;
}

// ---------------- mean pool over sorted batch (run-length local accumulation) ----------------
// block: 256 threads = 64 channels x 4 node-lanes; 128 nodes/block, 32 nodes/thread (stride 4).
__global__ void pool_kernel(const int* __restrict__ batch) {
    int tid = threadIdx.x;
    int c = tid & 63;
    int grp = tid >> 6;
    int base = blockIdx.x * 128;
    float acc = 0.f, cntacc = 0.f;
    int curb = -1;
    for (int j = 0; j < 32; j++) {
        int n = base + grp + j * 4;
        if (n >= N_NODES) break;
        int b = batch[n];
        if (b != curb) {
            if (curb >= 0) {
                atomicAdd(&g_psum[curb * CH + c], acc);
                if (c == 0) atomicAdd(&g_pcnt[curb], cntacc);
            }
            curb = b; acc = 0.f; cntacc = 0.f;
        }
        acc += g_H[n * CH + c] + g_HS[n * CH + c];
        cntacc += 1.0f;
    }
    if (curb >= 0) {
        atomicAdd(&g_psum[curb * CH + c], acc);
        if (c == 0) atomicAdd(&g_pcnt[curb], cntacc);
    }
}

// ---------------- final: out[g] = mean_pooled[g] . Wf + bf ----------------
__global__ void final_kernel(const float* __restrict__ Wf, const float* __restrict__ bf,
                             float* __restrict__ out) {
    int g = threadIdx.x;
    if (g >= N_GRAPHS) return;
    float inv = 1.0f / fmaxf(g_pcnt[g], 1.0f);
    float s = 0.f;
#pragma unroll
    for (int c = 0; c < CH; c++) s += (g_psum[g * CH + c] * inv) * Wf[c];
    out[g] = s + bf[0];
}

// ---------------- launch ----------------
extern "C" void kernel_launch(void* const* d_in, const int* in_sizes, int n_in,
                              void* d_out, int out_size) {
    const float* x    = (const float*)d_in[0];
    const float* xsc  = (const float*)d_in[1];
    const float* W1   = (const float*)d_in[2];
    const float* b1   = (const float*)d_in[3];
    const float* W2   = (const float*)d_in[4];
    const float* b2   = (const float*)d_in[5];
    const float* We   = (const float*)d_in[6];
    const float* be   = (const float*)d_in[7];
    const float* W1s  = (const float*)d_in[8];
    const float* b1s  = (const float*)d_in[9];
    const float* W2s  = (const float*)d_in[10];
    const float* b2s  = (const float*)d_in[11];
    const float* Wes  = (const float*)d_in[12];
    const float* bes  = (const float*)d_in[13];
    const float* Wf   = (const float*)d_in[14];
    const float* bf   = (const float*)d_in[15];
    const int*   ei   = (const int*)d_in[16];
    const int*   batch = (const int*)d_in[17];
    float* out = (float*)d_out;

    const int* e_src = ei;
    const int* e_dst = ei + N_EDGES;

    float *T, *S, *H, *HS;
    cudaGetSymbolAddress((void**)&T, g_T);
    cudaGetSymbolAddress((void**)&S, g_S);
    cudaGetSymbolAddress((void**)&H, g_H);
    cudaGetSymbolAddress((void**)&HS, g_HS);

    const int EB = 256;
    int egrid = (N_EDGES + EB - 1) / EB;
    int ggrid = (N_NODES + 127) / 128;                 // gemm: 391 blocks
    int pgrid = (N_NODES * 32 + 255) / 256;            // prop: warp per node

    // graph structure (rebuilt each replay; cheap, int atomics only)
    zero_kernel<<<(N_NODES + 255) / 256, 256>>>();
    hist_kernel<<<egrid, EB>>>(e_dst);
    scan_kernel<<<1, 1024>>>();
    fill_kernel<<<egrid, EB>>>(e_src, e_dst);

    // stack 1
    gemm64_kernel<<<ggrid, 128>>>(x, W1, T, N_NODES);
    gemm64_kernel<<<ggrid, 128>>>(x, We, S, N_NODES);
    prop_kernel<<<pgrid, 256>>>(T, b1, S, be, H, 1);
    gemm64_kernel<<<ggrid, 128>>>(H, W2, T, N_NODES);
    prop_kernel<<<pgrid, 256>>>(T, b2, H, nullptr, H, 0);

    // stack 2
    gemm64_kernel<<<ggrid, 128>>>(xsc, W1s, T, N_NODES);
    gemm64_kernel<<<ggrid, 128>>>(xsc, Wes, S, N_NODES);
    prop_kernel<<<pgrid, 256>>>(T, b1s, S, bes, HS, 1);
    gemm64_kernel<<<ggrid, 128>>>(HS, W2s, T, N_NODES);
    prop_kernel<<<pgrid, 256>>>(T, b2s, HS, nullptr, HS, 0);

    // pool + readout
    pool_kernel<<<(N_NODES + 127) / 128, 256>>>(batch);
    final_kernel<<<1, 64>>>(Wf, bf, out);
}

// round 5
// speedup vs baseline: 1.0798x; 1.0798x over previous
#include <cuda_runtime.h>
#include <cuda_bf16.h>

#define N_NODES 50000
#define N_EDGES 800000
#define N_GRAPHS 64
#define CH 64

// ---------------- scratch (static device globals; no allocation) ----------------
__device__ float g_T[N_NODES * CH];      // stack-1 gcn pre-act
__device__ float g_S[N_NODES * CH];      // stack-1 skip pre-act
__device__ float g_T2[N_NODES * CH];     // stack-2 gcn pre-act
__device__ float g_S2[N_NODES * CH];     // stack-2 skip pre-act
__device__ float g_H[N_NODES * CH];      // stack-1 state
__device__ float g_HS[N_NODES * CH];     // stack-2 state
__device__ float g_dinv[N_NODES];
__device__ int   g_cnt[N_NODES];
__device__ int   g_off[N_NODES + 1];
__device__ int   g_cursor[N_NODES];
__device__ int2  g_csredge[N_EDGES];     // {src, __float_as_int(norm)} packed
__device__ float g_psum[N_GRAPHS * CH];
__device__ float g_pcnt[N_GRAPHS];

// ---------------- zero scratch ----------------
__global__ void zero_kernel() {
    int i = blockIdx.x * blockDim.x + threadIdx.x;
    if (i < N_NODES) g_cnt[i] = 0;
    if (i < N_GRAPHS * CH) g_psum[i] = 0.f;
    if (i < N_GRAPHS) g_pcnt[i] = 0.f;
}

// ---------------- degree histogram ----------------
__global__ void hist_kernel(const int* __restrict__ dst) {
    int e = blockIdx.x * blockDim.x + threadIdx.x;
    if (e < N_EDGES) atomicAdd(&g_cnt[dst[e]], 1);
}

// ---------------- single-block exclusive scan + dinv ----------------
__global__ void scan_kernel() {
    __shared__ int part[1024];
    const int CHUNK = 49;
    int tid = threadIdx.x;
    int base = tid * CHUNK;
    int end = min(base + CHUNK, N_NODES);
    int sum = 0;
    for (int j = base; j < end; j++) sum += g_cnt[j];
    part[tid] = sum;
    __syncthreads();
    for (int d = 1; d < 1024; d <<= 1) {
        int v = (tid >= d) ? part[tid - d] : 0;
        __syncthreads();
        part[tid] += v;
        __syncthreads();
    }
    int run = part[tid] - sum;
    for (int j = base; j < end; j++) {
        g_off[j] = run;
        g_cursor[j] = run;
        int c = g_cnt[j];
        g_dinv[j] = rsqrtf(1.0f + (float)c);
        run += c;
    }
    if (tid == 0) g_off[N_NODES] = N_EDGES;
}

// ---------------- CSR fill: packed single STG.64 per edge ----------------
__global__ void fill_kernel(const int* __restrict__ src, const int* __restrict__ dst) {
    int e = blockIdx.x * blockDim.x + threadIdx.x;
    if (e < N_EDGES) {
        int s = src[e], d = dst[e];
        int slot = atomicAdd(&g_cursor[d], 1);
        float nm = g_dinv[s] * g_dinv[d];
        g_csredge[slot] = make_int2(s, __float_as_int(nm));
    }
}

// ---------------- fused single GEMM x2 stacks: Y = X @ W per stack ----------------
// gridDim.x = 2*nb; blocks [0,nb) -> stack A, [nb,2nb) -> stack B
__global__ void __launch_bounds__(128) gemm64_x2_kernel(const float* __restrict__ Xa,
                                                        const float* __restrict__ Wa_,
                                                        float* __restrict__ Ya,
                                                        const float* __restrict__ Xb,
                                                        const float* __restrict__ Wb_,
                                                        float* __restrict__ Yb,
                                                        int nrows, int nb) {
    __shared__ float sW[64 * 64];
    __shared__ float sX[64 * 128];
    int tid = threadIdx.x;
    int blk = blockIdx.x;
    const float* X; const float* W; float* Y;
    int rowBase;
    if (blk < nb) { X = Xa; W = Wa_; Y = Ya; rowBase = blk * 128; }
    else          { X = Xb; W = Wb_; Y = Yb; rowBase = (blk - nb) * 128; }

#pragma unroll
    for (int i = 0; i < 32; i++) sW[tid + i * 128] = W[tid + i * 128];

#pragma unroll
    for (int j = 0; j < 16; j++) {
        int idx4 = tid + j * 128;
        int r = idx4 >> 4;
        int kq = idx4 & 15;
        int grow = rowBase + r;
        float4 v = (grow < nrows) ? ((const float4*)X)[grow * 16 + kq]
                                  : make_float4(0.f, 0.f, 0.f, 0.f);
        sX[(kq * 4 + 0) * 128 + r] = v.x;
        sX[(kq * 4 + 1) * 128 + r] = v.y;
        sX[(kq * 4 + 2) * 128 + r] = v.z;
        sX[(kq * 4 + 3) * 128 + r] = v.w;
    }
    __syncthreads();

    int tx = tid & 7, ty = tid >> 3;
    int c0 = tx * 8, r0 = ty * 8;
    float acc[8][8];
#pragma unroll
    for (int i = 0; i < 8; i++)
#pragma unroll
        for (int j = 0; j < 8; j++) acc[i][j] = 0.f;

#pragma unroll 8
    for (int k = 0; k < 64; k++) {
        float4 w0 = *(const float4*)&sW[k * 64 + c0];
        float4 w1 = *(const float4*)&sW[k * 64 + c0 + 4];
        float4 x0 = *(const float4*)&sX[k * 128 + r0];
        float4 x1 = *(const float4*)&sX[k * 128 + r0 + 4];
        float xs[8] = {x0.x, x0.y, x0.z, x0.w, x1.x, x1.y, x1.z, x1.w};
        float ws[8] = {w0.x, w0.y, w0.z, w0.w, w1.x, w1.y, w1.z, w1.w};
#pragma unroll
        for (int ri = 0; ri < 8; ri++)
#pragma unroll
            for (int ci = 0; ci < 8; ci++) acc[ri][ci] += xs[ri] * ws[ci];
    }

#pragma unroll
    for (int ri = 0; ri < 8; ri++) {
        int row = rowBase + r0 + ri;
        if (row < nrows) {
            ((float4*)Y)[row * 16 + (c0 >> 2)] =
                make_float4(acc[ri][0], acc[ri][1], acc[ri][2], acc[ri][3]);
            ((float4*)Y)[row * 16 + (c0 >> 2) + 1] =
                make_float4(acc[ri][4], acc[ri][5], acc[ri][6], acc[ri][7]);
        }
    }
}

// ---------------- fused dual GEMM x2 stacks: (Ya=X@Wa, Yb=X@Wb) per stack ----------------
// 256 threads; 128 rows x 128 combined cols. blocks [0,nb): stack A, [nb,2nb): stack B.
__global__ void __launch_bounds__(256) gemm64_dual_x2_kernel(
        const float* __restrict__ X1, const float* __restrict__ W1a,
        const float* __restrict__ W1b, float* __restrict__ Y1a, float* __restrict__ Y1b,
        const float* __restrict__ X2, const float* __restrict__ W2a,
        const float* __restrict__ W2b, float* __restrict__ Y2a, float* __restrict__ Y2b,
        int nrows, int nb) {
    __shared__ float sW[64 * 128];
    __shared__ float sX[64 * 128];
    int tid = threadIdx.x;
    int blk = blockIdx.x;
    const float *X, *Wa, *Wb; float *Ya, *Yb;
    int rowBase;
    if (blk < nb) { X = X1; Wa = W1a; Wb = W1b; Ya = Y1a; Yb = Y1b; rowBase = blk * 128; }
    else          { X = X2; Wa = W2a; Wb = W2b; Ya = Y2a; Yb = Y2b; rowBase = (blk - nb) * 128; }

#pragma unroll
    for (int i = tid; i < 4096; i += 256) {
        int k = i >> 6, c = i & 63;
        sW[k * 128 + c] = Wa[i];
        sW[k * 128 + 64 + c] = Wb[i];
    }
#pragma unroll
    for (int j = 0; j < 8; j++) {
        int idx4 = tid + j * 256;
        int r = idx4 >> 4;
        int kq = idx4 & 15;
        int grow = rowBase + r;
        float4 v = (grow < nrows) ? ((const float4*)X)[grow * 16 + kq]
                                  : make_float4(0.f, 0.f, 0.f, 0.f);
        sX[(kq * 4 + 0) * 128 + r] = v.x;
        sX[(kq * 4 + 1) * 128 + r] = v.y;
        sX[(kq * 4 + 2) * 128 + r] = v.z;
        sX[(kq * 4 + 3) * 128 + r] = v.w;
    }
    __syncthreads();

    int tx = tid & 15, ty = tid >> 4;
    int c0 = tx * 8, r0 = ty * 8;
    float acc[8][8];
#pragma unroll
    for (int i = 0; i < 8; i++)
#pragma unroll
        for (int j = 0; j < 8; j++) acc[i][j] = 0.f;

#pragma unroll 4
    for (int k = 0; k < 64; k++) {
        float4 w0 = *(const float4*)&sW[k * 128 + c0];
        float4 w1 = *(const float4*)&sW[k * 128 + c0 + 4];
        float4 x0 = *(const float4*)&sX[k * 128 + r0];
        float4 x1 = *(const float4*)&sX[k * 128 + r0 + 4];
        float xs[8] = {x0.x, x0.y, x0.z, x0.w, x1.x, x1.y, x1.z, x1.w};
        float ws[8] = {w0.x, w0.y, w0.z, w0.w, w1.x, w1.y, w1.z, w1.w};
#pragma unroll
        for (int ri = 0; ri < 8; ri++)
#pragma unroll
            for (int ci = 0; ci < 8; ci++) acc[ri][ci] += xs[ri] * ws[ci];
    }

    float* Yout = (c0 < 64) ? Ya : Yb;
    int cc = (c0 < 64) ? c0 : (c0 - 64);
#pragma unroll
    for (int ri = 0; ri < 8; ri++) {
        int row = rowBase + r0 + ri;
        if (row < nrows) {
            ((float4*)Yout)[row * 16 + (cc >> 2)] =
                make_float4(acc[ri][0], acc[ri][1], acc[ri][2], acc[ri][3]);
            ((float4*)Yout)[row * 16 + (cc >> 2) + 1] =
                make_float4(acc[ri][4], acc[ri][5], acc[ri][6], acc[ri][7]);
        }
    }
}

// ---------------- fused propagation x2 stacks ----------------
// half-warp per (node,stack); nodes [0,N): stack A, [N,2N): stack B.
__global__ void __launch_bounds__(256) prop_x2_kernel(
        const float* __restrict__ Ta, const float* __restrict__ biasa,
        const float* __restrict__ adda, const float* __restrict__ addba,
        float* __restrict__ Houta,
        const float* __restrict__ Tb, const float* __restrict__ biasb,
        const float* __restrict__ addb, const float* __restrict__ addbb,
        float* __restrict__ Houtb, int relu_add) {
    int lane = threadIdx.x & 31;
    int warp = threadIdx.x >> 5;
    int q = lane & 15;
    int slot = (blockIdx.x * 8 + warp) * 2 + (lane >> 4);   // [0, 2N)
    if (slot >= 2 * N_NODES) return;

    const float* T; const float* bias; const float* add_in; const float* add_bias;
    float* Hout; int node;
    if (slot < N_NODES) { T = Ta; bias = biasa; add_in = adda; add_bias = addba; Hout = Houta; node = slot; }
    else                { T = Tb; bias = biasb; add_in = addb; add_bias = addbb; Hout = Houtb; node = slot - N_NODES; }

    const float4* T4 = (const float4*)T;
    int s0 = g_off[node], s1 = g_off[node + 1];
    float4 acc = make_float4(0.f, 0.f, 0.f, 0.f);

    int s = s0;
    for (; s + 2 <= s1; s += 2) {
        int2 e0 = g_csredge[s];
        int2 e1 = g_csredge[s + 1];
        float4 v0 = T4[e0.x * 16 + q];
        float4 v1 = T4[e1.x * 16 + q];
        float n0 = __int_as_float(e0.y), n1 = __int_as_float(e1.y);
        acc.x = fmaf(n0, v0.x, acc.x); acc.y = fmaf(n0, v0.y, acc.y);
        acc.z = fmaf(n0, v0.z, acc.z); acc.w = fmaf(n0, v0.w, acc.w);
        acc.x = fmaf(n1, v1.x, acc.x); acc.y = fmaf(n1, v1.y, acc.y);
        acc.z = fmaf(n1, v1.z, acc.z); acc.w = fmaf(n1, v1.w, acc.w);
    }
    if (s < s1) {
        int2 e0 = g_csredge[s];
        float4 v0 = T4[e0.x * 16 + q];
        float n0 = __int_as_float(e0.y);
        acc.x = fmaf(n0, v0.x, acc.x); acc.y = fmaf(n0, v0.y, acc.y);
        acc.z = fmaf(n0, v0.z, acc.z); acc.w = fmaf(n0, v0.w, acc.w);
    }

    float dv = g_dinv[node];
    float sn = dv * dv;
    float4 tv = T4[node * 16 + q];
    float4 bv = ((const float4*)bias)[q];
    float4 g;
    g.x = fmaxf(fmaf(sn, tv.x, acc.x) + bv.x, 0.f);
    g.y = fmaxf(fmaf(sn, tv.y, acc.y) + bv.y, 0.f);
    g.z = fmaxf(fmaf(sn, tv.z, acc.z) + bv.z, 0.f);
    g.w = fmaxf(fmaf(sn, tv.w, acc.w) + bv.w, 0.f);

    float4 av = ((const float4*)add_in)[node * 16 + q];
    if (relu_add) {
        float4 ab = ((const float4*)add_bias)[q];
        av.x = fmaxf(av.x + ab.x, 0.f);
        av.y = fmaxf(av.y + ab.y, 0.f);
        av.z = fmaxf(av.z + ab.z, 0.f);
        av.w = fmaxf(av.w + ab.w, 0.f);
    }
    ((float4*)Hout)[node * 16 + q] =
        make_float4(g.x + av.x, g.y + av.y, g.z + av.z, g.w + av.w);
}

// ---------------- mean pool over sorted batch ----------------
__global__ void pool_kernel(const int* __restrict__ batch) {
    int tid = threadIdx.x;
    int c = tid & 63;
    int grp = tid >> 6;
    int base = blockIdx.x * 128;
    float acc = 0.f, cntacc = 0.f;
    int curb = -1;
    for (int j = 0; j < 32; j++) {
        int n = base + grp + j * 4;
        if (n >= N_NODES) break;
        int b = batch[n];
        if (b != curb) {
            if (curb >= 0) {
                atomicAdd(&g_psum[curb * CH + c], acc);
                if (c == 0) atomicAdd(&g_pcnt[curb], cntacc);
            }
            curb = b; acc = 0.f; cntacc = 0.f;
        }
        acc += g_H[n * CH + c] + g_HS[n * CH + c];
        cntacc += 1.0f;
    }
    if (curb >= 0) {
        atomicAdd(&g_psum[curb * CH + c], acc);
        if (c == 0) atomicAdd(&g_pcnt[curb], cntacc);
    }
}

// ---------------- final readout ----------------
__global__ void final_kernel(const float* __restrict__ Wf, const float* __restrict__ bf,
                             float* __restrict__ out) {
    int g = threadIdx.x;
    if (g >= N_GRAPHS) return;
    float inv = 1.0f / fmaxf(g_pcnt[g], 1.0f);
    float s = 0.f;
#pragma unroll
    for (int c = 0; c < CH; c++) s += (g_psum[g * CH + c] * inv) * Wf[c];
    out[g] = s + bf[0];
}

// ---------------- launch ----------------
extern "C" void kernel_launch(void* const* d_in, const int* in_sizes, int n_in,
                              void* d_out, int out_size) {
    const float* x    = (const float*)d_in[0];
    const float* xsc  = (const float*)d_in[1];
    const float* W1   = (const float*)d_in[2];
    const float* b1   = (const float*)d_in[3];
    const float* W2   = (const float*)d_in[4];
    const float* b2   = (const float*)d_in[5];
    const float* We   = (const float*)d_in[6];
    const float* be   = (const float*)d_in[7];
    const float* W1s  = (const float*)d_in[8];
    const float* b1s  = (const float*)d_in[9];
    const float* W2s  = (const float*)d_in[10];
    const float* b2s  = (const float*)d_in[11];
    const float* Wes  = (const float*)d_in[12];
    const float* bes  = (const float*)d_in[13];
    const float* Wf   = (const float*)d_in[14];
    const float* bf   = (const float*)d_in[15];
    const int*   ei   = (const int*)d_in[16];
    const int*   batch = (const int*)d_in[17];
    float* out = (float*)d_out;

    const int* e_src = ei;
    const int* e_dst = ei + N_EDGES;

    float *T, *S, *T2, *S2, *H, *HS;
    cudaGetSymbolAddress((void**)&T, g_T);
    cudaGetSymbolAddress((void**)&S, g_S);
    cudaGetSymbolAddress((void**)&T2, g_T2);
    cudaGetSymbolAddress((void**)&S2, g_S2);
    cudaGetSymbolAddress((void**)&H, g_H);
    cudaGetSymbolAddress((void**)&HS, g_HS);

    const int EB = 256;
    int egrid = (N_EDGES + EB - 1) / EB;
    int nb = (N_NODES + 127) / 128;                     // 391 blocks per stack
    int pgrid2 = (2 * N_NODES + 15) / 16;               // fused prop: 6250 blocks

    // graph structure
    zero_kernel<<<(N_NODES + 255) / 256, 256>>>();
    hist_kernel<<<egrid, EB>>>(e_dst);
    scan_kernel<<<1, 1024>>>();
    fill_kernel<<<egrid, EB>>>(e_src, e_dst);

    // layer 1 (both stacks fused): T=x@W1, S=x@We | T2=xsc@W1s, S2=xsc@Wes
    gemm64_dual_x2_kernel<<<2 * nb, 256>>>(x, W1, We, T, S,
                                           xsc, W1s, Wes, T2, S2, N_NODES, nb);
    // prop layer 1 (both stacks fused)
    prop_x2_kernel<<<pgrid2, 256>>>(T, b1, S, be, H,
                                    T2, b1s, S2, bes, HS, 1);
    // layer 2 GEMM (both stacks fused): T=H@W2 | T2=HS@W2s
    gemm64_x2_kernel<<<2 * nb, 128>>>(H, W2, T, HS, W2s, T2, N_NODES, nb);
    // prop layer 2 (both stacks fused)
    prop_x2_kernel<<<pgrid2, 256>>>(T, b2, H, nullptr, H,
                                    T2, b2s, HS, nullptr, HS, 0);

    // pool + readout
    pool_kernel<<<(N_NODES + 127) / 128, 256>>>(batch);
    final_kernel<<<1, 64>>>(Wf, bf, out);
}

// round 8
// speedup vs baseline: 1.6359x; 1.5149x over previous
#include <cuda_runtime.h>
#include <cuda_bf16.h>

#define N_NODES 50000
#define N_EDGES 800000
#define N_GRAPHS 64
#define CH 64
#define SCAN_BLOCKS 196   // 196*256 = 50176 >= N_NODES

// ---------------- scratch (static device globals; no allocation) ----------------
__device__ float g_T[N_NODES * CH];      // stack-1 gcn pre-act
__device__ float g_S[N_NODES * CH];      // stack-1 skip pre-act
__device__ float g_T2[N_NODES * CH];     // stack-2 gcn pre-act
__device__ float g_S2[N_NODES * CH];     // stack-2 skip pre-act
__device__ float g_H[N_NODES * CH];      // stack-1 state
__device__ float g_HS[N_NODES * CH];     // stack-2 state
__device__ float g_dinv[N_NODES];
__device__ int   g_cnt[N_NODES];
__device__ int   g_off[N_NODES + 1];
__device__ int   g_cursor[N_NODES];
__device__ int   g_bsum[SCAN_BLOCKS];
__device__ int   g_btop[SCAN_BLOCKS];
__device__ int2  g_csredge[N_EDGES];     // {src, __float_as_int(norm)} packed
__device__ float g_psum[N_GRAPHS * CH];
__device__ float g_pcnt[N_GRAPHS];

// ---------------- zero scratch ----------------
__global__ void zero_kernel() {
    int i = blockIdx.x * blockDim.x + threadIdx.x;
    if (i < N_NODES) g_cnt[i] = 0;
    if (i < N_GRAPHS * CH) g_psum[i] = 0.f;
    if (i < N_GRAPHS) g_pcnt[i] = 0.f;
}

// ---------------- degree histogram, 4 edges/thread (int4 loads) ----------------
__global__ void hist_kernel(const int* __restrict__ dst) {
    int t = blockIdx.x * blockDim.x + threadIdx.x;      // t in [0, N_EDGES/4)
    if (t * 4 < N_EDGES) {
        int4 d = ((const int4*)dst)[t];
        atomicAdd(&g_cnt[d.x], 1);
        atomicAdd(&g_cnt[d.y], 1);
        atomicAdd(&g_cnt[d.z], 1);
        atomicAdd(&g_cnt[d.w], 1);
    }
}

// ---------------- parallel 3-phase scan ----------------
__global__ void scan1_kernel() {   // per-block sums
    __shared__ int sh[256];
    int tid = threadIdx.x;
    int i = blockIdx.x * 256 + tid;
    int c = (i < N_NODES) ? g_cnt[i] : 0;
    sh[tid] = c;
    __syncthreads();
    for (int d = 128; d > 0; d >>= 1) {
        if (tid < d) sh[tid] += sh[tid + d];
        __syncthreads();
    }
    if (tid == 0) g_bsum[blockIdx.x] = sh[0];
}

__global__ void scan2_kernel() {   // tiny top-level exclusive scan (1 block)
    __shared__ int sh[256];
    int tid = threadIdx.x;
    int v = (tid < SCAN_BLOCKS) ? g_bsum[tid] : 0;
    sh[tid] = v;
    __syncthreads();
    for (int d = 1; d < 256; d <<= 1) {
        int t = (tid >= d) ? sh[tid - d] : 0;
        __syncthreads();
        sh[tid] += t;
        __syncthreads();
    }
    if (tid < SCAN_BLOCKS) g_btop[tid] = sh[tid] - v;   // exclusive
    if (tid == 0) g_off[N_NODES] = N_EDGES;
}

__global__ void scan3_kernel() {   // apply: per-node offsets + cursor + dinv
    __shared__ int sh[256];
    int tid = threadIdx.x;
    int i = blockIdx.x * 256 + tid;
    int c = (i < N_NODES) ? g_cnt[i] : 0;
    sh[tid] = c;
    __syncthreads();
    for (int d = 1; d < 256; d <<= 1) {
        int t = (tid >= d) ? sh[tid - d] : 0;
        __syncthreads();
        sh[tid] += t;
        __syncthreads();
    }
    if (i < N_NODES) {
        int off = g_btop[blockIdx.x] + sh[tid] - c;     // exclusive prefix
        g_off[i] = off;
        g_cursor[i] = off;
        g_dinv[i] = rsqrtf(1.0f + (float)c);
    }
}

// ---------------- CSR fill: 4 edges/thread, packed STG.64 ----------------
__global__ void fill_kernel(const int* __restrict__ src, const int* __restrict__ dst) {
    int t = blockIdx.x * blockDim.x + threadIdx.x;
    if (t * 4 < N_EDGES) {
        int4 s4 = ((const int4*)src)[t];
        int4 d4 = ((const int4*)dst)[t];
        float is0 = g_dinv[s4.x], id0 = g_dinv[d4.x];
        float is1 = g_dinv[s4.y], id1 = g_dinv[d4.y];
        float is2 = g_dinv[s4.z], id2 = g_dinv[d4.z];
        float is3 = g_dinv[s4.w], id3 = g_dinv[d4.w];
        int p0 = atomicAdd(&g_cursor[d4.x], 1);
        int p1 = atomicAdd(&g_cursor[d4.y], 1);
        int p2 = atomicAdd(&g_cursor[d4.z], 1);
        int p3 = atomicAdd(&g_cursor[d4.w], 1);
        g_csredge[p0] = make_int2(s4.x, __float_as_int(is0 * id0));
        g_csredge[p1] = make_int2(s4.y, __float_as_int(is1 * id1));
        g_csredge[p2] = make_int2(s4.z, __float_as_int(is2 * id2));
        g_csredge[p3] = make_int2(s4.w, __float_as_int(is3 * id3));
    }
}

// ---------------- fused single GEMM x2 stacks ----------------
__global__ void __launch_bounds__(128) gemm64_x2_kernel(const float* __restrict__ Xa,
                                                        const float* __restrict__ Wa_,
                                                        float* __restrict__ Ya,
                                                        const float* __restrict__ Xb,
                                                        const float* __restrict__ Wb_,
                                                        float* __restrict__ Yb,
                                                        int nrows, int nb) {
    __shared__ float sW[64 * 64];
    __shared__ float sX[64 * 128];
    int tid = threadIdx.x;
    int blk = blockIdx.x;
    const float* X; const float* W; float* Y;
    int rowBase;
    if (blk < nb) { X = Xa; W = Wa_; Y = Ya; rowBase = blk * 128; }
    else          { X = Xb; W = Wb_; Y = Yb; rowBase = (blk - nb) * 128; }

#pragma unroll
    for (int i = 0; i < 32; i++) sW[tid + i * 128] = W[tid + i * 128];

#pragma unroll
    for (int j = 0; j < 16; j++) {
        int idx4 = tid + j * 128;
        int r = idx4 >> 4;
        int kq = idx4 & 15;
        int grow = rowBase + r;
        float4 v = (grow < nrows) ? ((const float4*)X)[grow * 16 + kq]
                                  : make_float4(0.f, 0.f, 0.f, 0.f);
        sX[(kq * 4 + 0) * 128 + r] = v.x;
        sX[(kq * 4 + 1) * 128 + r] = v.y;
        sX[(kq * 4 + 2) * 128 + r] = v.z;
        sX[(kq * 4 + 3) * 128 + r] = v.w;
    }
    __syncthreads();

    int tx = tid & 7, ty = tid >> 3;
    int c0 = tx * 8, r0 = ty * 8;
    float acc[8][8];
#pragma unroll
    for (int i = 0; i < 8; i++)
#pragma unroll
        for (int j = 0; j < 8; j++) acc[i][j] = 0.f;

#pragma unroll 8
    for (int k = 0; k < 64; k++) {
        float4 w0 = *(const float4*)&sW[k * 64 + c0];
        float4 w1 = *(const float4*)&sW[k * 64 + c0 + 4];
        float4 x0 = *(const float4*)&sX[k * 128 + r0];
        float4 x1 = *(const float4*)&sX[k * 128 + r0 + 4];
        float xs[8] = {x0.x, x0.y, x0.z, x0.w, x1.x, x1.y, x1.z, x1.w};
        float ws[8] = {w0.x, w0.y, w0.z, w0.w, w1.x, w1.y, w1.z, w1.w};
#pragma unroll
        for (int ri = 0; ri < 8; ri++)
#pragma unroll
            for (int ci = 0; ci < 8; ci++) acc[ri][ci] += xs[ri] * ws[ci];
    }

#pragma unroll
    for (int ri = 0; ri < 8; ri++) {
        int row = rowBase + r0 + ri;
        if (row < nrows) {
            ((float4*)Y)[row * 16 + (c0 >> 2)] =
                make_float4(acc[ri][0], acc[ri][1], acc[ri][2], acc[ri][3]);
            ((float4*)Y)[row * 16 + (c0 >> 2) + 1] =
                make_float4(acc[ri][4], acc[ri][5], acc[ri][6], acc[ri][7]);
        }
    }
}

// ---------------- fused dual GEMM x2 stacks ----------------
__global__ void __launch_bounds__(256) gemm64_dual_x2_kernel(
        const float* __restrict__ X1, const float* __restrict__ W1a,
        const float* __restrict__ W1b, float* __restrict__ Y1a, float* __restrict__ Y1b,
        const float* __restrict__ X2, const float* __restrict__ W2a,
        const float* __restrict__ W2b, float* __restrict__ Y2a, float* __restrict__ Y2b,
        int nrows, int nb) {
    __shared__ float sW[64 * 128];
    __shared__ float sX[64 * 128];
    int tid = threadIdx.x;
    int blk = blockIdx.x;
    const float *X, *Wa, *Wb; float *Ya, *Yb;
    int rowBase;
    if (blk < nb) { X = X1; Wa = W1a; Wb = W1b; Ya = Y1a; Yb = Y1b; rowBase = blk * 128; }
    else          { X = X2; Wa = W2a; Wb = W2b; Ya = Y2a; Yb = Y2b; rowBase = (blk - nb) * 128; }

#pragma unroll
    for (int i = tid; i < 4096; i += 256) {
        int k = i >> 6, c = i & 63;
        sW[k * 128 + c] = Wa[i];
        sW[k * 128 + 64 + c] = Wb[i];
    }
#pragma unroll
    for (int j = 0; j < 8; j++) {
        int idx4 = tid + j * 256;
        int r = idx4 >> 4;
        int kq = idx4 & 15;
        int grow = rowBase + r;
        float4 v = (grow < nrows) ? ((const float4*)X)[grow * 16 + kq]
                                  : make_float4(0.f, 0.f, 0.f, 0.f);
        sX[(kq * 4 + 0) * 128 + r] = v.x;
        sX[(kq * 4 + 1) * 128 + r] = v.y;
        sX[(kq * 4 + 2) * 128 + r] = v.z;
        sX[(kq * 4 + 3) * 128 + r] = v.w;
    }
    __syncthreads();

    int tx = tid & 15, ty = tid >> 4;
    int c0 = tx * 8, r0 = ty * 8;
    float acc[8][8];
#pragma unroll
    for (int i = 0; i < 8; i++)
#pragma unroll
        for (int j = 0; j < 8; j++) acc[i][j] = 0.f;

#pragma unroll 4
    for (int k = 0; k < 64; k++) {
        float4 w0 = *(const float4*)&sW[k * 128 + c0];
        float4 w1 = *(const float4*)&sW[k * 128 + c0 + 4];
        float4 x0 = *(const float4*)&sX[k * 128 + r0];
        float4 x1 = *(const float4*)&sX[k * 128 + r0 + 4];
        float xs[8] = {x0.x, x0.y, x0.z, x0.w, x1.x, x1.y, x1.z, x1.w};
        float ws[8] = {w0.x, w0.y, w0.z, w0.w, w1.x, w1.y, w1.z, w1.w};
#pragma unroll
        for (int ri = 0; ri < 8; ri++)
#pragma unroll
            for (int ci = 0; ci < 8; ci++) acc[ri][ci] += xs[ri] * ws[ci];
    }

    float* Yout = (c0 < 64) ? Ya : Yb;
    int cc = (c0 < 64) ? c0 : (c0 - 64);
#pragma unroll
    for (int ri = 0; ri < 8; ri++) {
        int row = rowBase + r0 + ri;
        if (row < nrows) {
            ((float4*)Yout)[row * 16 + (cc >> 2)] =
                make_float4(acc[ri][0], acc[ri][1], acc[ri][2], acc[ri][3]);
            ((float4*)Yout)[row * 16 + (cc >> 2) + 1] =
                make_float4(acc[ri][4], acc[ri][5], acc[ri][6], acc[ri][7]);
        }
    }
}

// ---------------- propagation: BOTH stacks per edge, unroll-4 ----------------
#define EDGE_FMA(e, va, vb)                                                        \
    {                                                                              \
        float nm = __int_as_float(e.y);                                            \
        acca.x = fmaf(nm, va.x, acca.x); acca.y = fmaf(nm, va.y, acca.y);          \
        acca.z = fmaf(nm, va.z, acca.z); acca.w = fmaf(nm, va.w, acca.w);          \
        accb.x = fmaf(nm, vb.x, accb.x); accb.y = fmaf(nm, vb.y, accb.y);          \
        accb.z = fmaf(nm, vb.z, accb.z); accb.w = fmaf(nm, vb.w, accb.w);          \
    }

__global__ void __launch_bounds__(256) prop_both_kernel(
        const float* __restrict__ Ta, const float* __restrict__ biasa,
        const float* __restrict__ adda, const float* __restrict__ addba,
        float* __restrict__ Houta,
        const float* __restrict__ Tb, const float* __restrict__ biasb,
        const float* __restrict__ addb, const float* __restrict__ addbb,
        float* __restrict__ Houtb, int relu_add) {
    int lane = threadIdx.x & 31;
    int warp = threadIdx.x >> 5;
    int q = lane & 15;
    int node = (blockIdx.x * 8 + warp) * 2 + (lane >> 4);
    if (node >= N_NODES) return;

    const float4* Ta4 = (const float4*)Ta;
    const float4* Tb4 = (const float4*)Tb;
    int s0 = g_off[node], s1 = g_off[node + 1];
    float4 acca = make_float4(0.f, 0.f, 0.f, 0.f);
    float4 accb = make_float4(0.f, 0.f, 0.f, 0.f);

    int s = s0;
    for (; s + 4 <= s1; s += 4) {
        int2 e0 = g_csredge[s];
        int2 e1 = g_csredge[s + 1];
        int2 e2 = g_csredge[s + 2];
        int2 e3 = g_csredge[s + 3];
        float4 va0 = Ta4[e0.x * 16 + q], vb0 = Tb4[e0.x * 16 + q];
        float4 va1 = Ta4[e1.x * 16 + q], vb1 = Tb4[e1.x * 16 + q];
        float4 va2 = Ta4[e2.x * 16 + q], vb2 = Tb4[e2.x * 16 + q];
        float4 va3 = Ta4[e3.x * 16 + q], vb3 = Tb4[e3.x * 16 + q];
        EDGE_FMA(e0, va0, vb0);
        EDGE_FMA(e1, va1, vb1);
        EDGE_FMA(e2, va2, vb2);
        EDGE_FMA(e3, va3, vb3);
    }
    for (; s < s1; s++) {
        int2 e0 = g_csredge[s];
        float4 va0 = Ta4[e0.x * 16 + q], vb0 = Tb4[e0.x * 16 + q];
        EDGE_FMA(e0, va0, vb0);
    }

    float dv = g_dinv[node];
    float sn = dv * dv;
    // stack A combine
    {
        float4 tv = Ta4[node * 16 + q];
        float4 bv = ((const float4*)biasa)[q];
        float4 g;
        g.x = fmaxf(fmaf(sn, tv.x, acca.x) + bv.x, 0.f);
        g.y = fmaxf(fmaf(sn, tv.y, acca.y) + bv.y, 0.f);
        g.z = fmaxf(fmaf(sn, tv.z, acca.z) + bv.z, 0.f);
        g.w = fmaxf(fmaf(sn, tv.w, acca.w) + bv.w, 0.f);
        float4 av = ((const float4*)adda)[node * 16 + q];
        if (relu_add) {
            float4 ab = ((const float4*)addba)[q];
            av.x = fmaxf(av.x + ab.x, 0.f);
            av.y = fmaxf(av.y + ab.y, 0.f);
            av.z = fmaxf(av.z + ab.z, 0.f);
            av.w = fmaxf(av.w + ab.w, 0.f);
        }
        ((float4*)Houta)[node * 16 + q] =
            make_float4(g.x + av.x, g.y + av.y, g.z + av.z, g.w + av.w);
    }
    // stack B combine
    {
        float4 tv = Tb4[node * 16 + q];
        float4 bv = ((const float4*)biasb)[q];
        float4 g;
        g.x = fmaxf(fmaf(sn, tv.x, accb.x) + bv.x, 0.f);
        g.y = fmaxf(fmaf(sn, tv.y, accb.y) + bv.y, 0.f);
        g.z = fmaxf(fmaf(sn, tv.z, accb.z) + bv.z, 0.f);
        g.w = fmaxf(fmaf(sn, tv.w, accb.w) + bv.w, 0.f);
        float4 av = ((const float4*)addb)[node * 16 + q];
        if (relu_add) {
            float4 ab = ((const float4*)addbb)[q];
            av.x = fmaxf(av.x + ab.x, 0.f);
            av.y = fmaxf(av.y + ab.y, 0.f);
            av.z = fmaxf(av.z + ab.z, 0.f);
            av.w = fmaxf(av.w + ab.w, 0.f);
        }
        ((float4*)Houtb)[node * 16 + q] =
            make_float4(g.x + av.x, g.y + av.y, g.z + av.z, g.w + av.w);
    }
}

// ---------------- mean pool over sorted batch ----------------
__global__ void pool_kernel(const int* __restrict__ batch) {
    int tid = threadIdx.x;
    int c = tid & 63;
    int grp = tid >> 6;
    int base = blockIdx.x * 128;
    float acc = 0.f, cntacc = 0.f;
    int curb = -1;
    for (int j = 0; j < 32; j++) {
        int n = base + grp + j * 4;
        if (n >= N_NODES) break;
        int b = batch[n];
        if (b != curb) {
            if (curb >= 0) {
                atomicAdd(&g_psum[curb * CH + c], acc);
                if (c == 0) atomicAdd(&g_pcnt[curb], cntacc);
            }
            curb = b; acc = 0.f; cntacc = 0.f;
        }
        acc += g_H[n * CH + c] + g_HS[n * CH + c];
        cntacc += 1.0f;
    }
    if (curb >= 0) {
        atomicAdd(&g_psum[curb * CH + c], acc);
        if (c == 0) atomicAdd(&g_pcnt[curb], cntacc);
    }
}

// ---------------- final readout ----------------
__global__ void final_kernel(const float* __restrict__ Wf, const float* __restrict__ bf,
                             float* __restrict__ out) {
    int g = threadIdx.x;
    if (g >= N_GRAPHS) return;
    float inv = 1.0f / fmaxf(g_pcnt[g], 1.0f);
    float s = 0.f;
#pragma unroll
    for (int c = 0; c < CH; c++) s += (g_psum[g * CH + c] * inv) * Wf[c];
    out[g] = s + bf[0];
}

// ---------------- launch ----------------
extern "C" void kernel_launch(void* const* d_in, const int* in_sizes, int n_in,
                              void* d_out, int out_size) {
    const float* x    = (const float*)d_in[0];
    const float* xsc  = (const float*)d_in[1];
    const float* W1   = (const float*)d_in[2];
    const float* b1   = (const float*)d_in[3];
    const float* W2   = (const float*)d_in[4];
    const float* b2   = (const float*)d_in[5];
    const float* We   = (const float*)d_in[6];
    const float* be   = (const float*)d_in[7];
    const float* W1s  = (const float*)d_in[8];
    const float* b1s  = (const float*)d_in[9];
    const float* W2s  = (const float*)d_in[10];
    const float* b2s  = (const float*)d_in[11];
    const float* Wes  = (const float*)d_in[12];
    const float* bes  = (const float*)d_in[13];
    const float* Wf   = (const float*)d_in[14];
    const float* bf   = (const float*)d_in[15];
    const int*   ei   = (const int*)d_in[16];
    const int*   batch = (const int*)d_in[17];
    float* out = (float*)d_out;

    const int* e_src = ei;
    const int* e_dst = ei + N_EDGES;

    float *T, *S, *T2, *S2, *H, *HS;
    cudaGetSymbolAddress((void**)&T, g_T);
    cudaGetSymbolAddress((void**)&S, g_S);
    cudaGetSymbolAddress((void**)&T2, g_T2);
    cudaGetSymbolAddress((void**)&S2, g_S2);
    cudaGetSymbolAddress((void**)&H, g_H);
    cudaGetSymbolAddress((void**)&HS, g_HS);

    int e4grid = (N_EDGES / 4 + 255) / 256;             // 782 blocks (4 edges/thread)
    int nb = (N_NODES + 127) / 128;                     // 391 blocks per stack
    int pgrid = (N_NODES + 15) / 16;                    // both-stack prop: 3125 blocks

    // graph structure
    zero_kernel<<<(N_NODES + 255) / 256, 256>>>();
    hist_kernel<<<e4grid, 256>>>(e_dst);
    scan1_kernel<<<SCAN_BLOCKS, 256>>>();
    scan2_kernel<<<1, 256>>>();
    scan3_kernel<<<SCAN_BLOCKS, 256>>>();
    fill_kernel<<<e4grid, 256>>>(e_src, e_dst);

    // layer 1: T=x@W1, S=x@We | T2=xsc@W1s, S2=xsc@Wes (fused both stacks)
    gemm64_dual_x2_kernel<<<2 * nb, 256>>>(x, W1, We, T, S,
                                           xsc, W1s, Wes, T2, S2, N_NODES, nb);
    // prop layer 1 (both stacks per edge)
    prop_both_kernel<<<pgrid, 256>>>(T, b1, S, be, H,
                                     T2, b1s, S2, bes, HS, 1);
    // layer 2 GEMM: T=H@W2 | T2=HS@W2s
    gemm64_x2_kernel<<<2 * nb, 128>>>(H, W2, T, HS, W2s, T2, N_NODES, nb);
    // prop layer 2 (both stacks per edge)
    prop_both_kernel<<<pgrid, 256>>>(T, b2, H, nullptr, H,
                                     T2, b2s, HS, nullptr, HS, 0);

    // pool + readout
    pool_kernel<<<(N_NODES + 127) / 128, 256>>>(batch);
    final_kernel<<<1, 64>>>(Wf, bf, out);
}

// round 13
// speedup vs baseline: 1.6684x; 1.0199x over previous
#include <cuda_runtime.h>
#include <cuda_bf16.h>

#define N_NODES 50000
#define N_EDGES 800000
#define N_GRAPHS 64
#define CH 64
#define SCAN_BLOCKS 196   // 196*256 = 50176 >= N_NODES

// ---------------- packed f32x2 helpers (sm_103a FFMA2 path) ----------------
__device__ __forceinline__ unsigned long long fma2(unsigned long long a,
                                                   unsigned long long b,
                                                   unsigned long long c) {
    unsigned long long d;
    asm("fma.rn.f32x2 %0, %1, %2, %3;" : "=l"(d) : "l"(a), "l"(b), "l"(c));
    return d;
}
__device__ __forceinline__ unsigned long long pack2(float x, float y) {
    unsigned long long r;
    asm("mov.b64 %0, {%1, %2};" : "=l"(r) : "f"(x), "f"(y));
    return r;
}

// ---------------- scratch (static device globals; no allocation) ----------------
__device__ float g_T[N_NODES * CH];      // stack-1 gcn pre-act
__device__ float g_S[N_NODES * CH];      // stack-1 skip pre-act
__device__ float g_T2[N_NODES * CH];     // stack-2 gcn pre-act
__device__ float g_S2[N_NODES * CH];     // stack-2 skip pre-act
__device__ float g_H[N_NODES * CH];      // stack-1 state
__device__ float g_HS[N_NODES * CH];     // stack-2 state
__device__ float g_dinv[N_NODES];
__device__ int   g_cnt[N_NODES];
__device__ int2  g_offcnt[N_NODES];      // {bucket offset, count}
__device__ int   g_cursor[N_NODES];
__device__ int   g_counter;              // global bucket allocator
__device__ int2  g_csredge[N_EDGES];     // {src, __float_as_int(norm)} packed
__device__ float g_psum[N_GRAPHS * CH];
__device__ float g_pcnt[N_GRAPHS];

// ---------------- zero scratch ----------------
__global__ void zero_kernel() {
    int i = blockIdx.x * blockDim.x + threadIdx.x;
    if (i < N_NODES) g_cnt[i] = 0;
    if (i < N_GRAPHS * CH) g_psum[i] = 0.f;
    if (i < N_GRAPHS) g_pcnt[i] = 0.f;
    if (i == 0) g_counter = 0;
}

// ---------------- degree histogram, 4 edges/thread (int4 loads) ----------------
__global__ void hist_kernel(const int* __restrict__ dst) {
    int t = blockIdx.x * blockDim.x + threadIdx.x;      // t in [0, N_EDGES/4)
    if (t * 4 < N_EDGES) {
        int4 d = ((const int4*)dst)[t];
        atomicAdd(&g_cnt[d.x], 1);
        atomicAdd(&g_cnt[d.y], 1);
        atomicAdd(&g_cnt[d.z], 1);
        atomicAdd(&g_cnt[d.w], 1);
    }
}

// ---------------- fused single-kernel scan: atomic block-base allocation ----------------
// Bucket regions need not be in node order; prop uses (off, cnt) pairs.
__global__ void scan_fused_kernel() {
    __shared__ int sh[256];
    __shared__ int base_sh;
    int tid = threadIdx.x;
    int i = blockIdx.x * 256 + tid;
    int c = (i < N_NODES) ? g_cnt[i] : 0;
    sh[tid] = c;
    __syncthreads();
    for (int d = 1; d < 256; d <<= 1) {
        int t = (tid >= d) ? sh[tid - d] : 0;
        __syncthreads();
        sh[tid] += t;
        __syncthreads();
    }
    if (tid == 0) base_sh = atomicAdd(&g_counter, sh[255]);
    __syncthreads();
    if (i < N_NODES) {
        int off = base_sh + sh[tid] - c;    // exclusive prefix within block + block base
        g_offcnt[i] = make_int2(off, c);
        g_cursor[i] = off;
        g_dinv[i] = rsqrtf(1.0f + (float)c);
    }
}

// ---------------- CSR fill: 4 edges/thread, packed STG.64 ----------------
__global__ void fill_kernel(const int* __restrict__ src, const int* __restrict__ dst) {
    int t = blockIdx.x * blockDim.x + threadIdx.x;
    if (t * 4 < N_EDGES) {
        int4 s4 = ((const int4*)src)[t];
        int4 d4 = ((const int4*)dst)[t];
        float is0 = g_dinv[s4.x], id0 = g_dinv[d4.x];
        float is1 = g_dinv[s4.y], id1 = g_dinv[d4.y];
        float is2 = g_dinv[s4.z], id2 = g_dinv[d4.z];
        float is3 = g_dinv[s4.w], id3 = g_dinv[d4.w];
        int p0 = atomicAdd(&g_cursor[d4.x], 1);
        int p1 = atomicAdd(&g_cursor[d4.y], 1);
        int p2 = atomicAdd(&g_cursor[d4.z], 1);
        int p3 = atomicAdd(&g_cursor[d4.w], 1);
        g_csredge[p0] = make_int2(s4.x, __float_as_int(is0 * id0));
        g_csredge[p1] = make_int2(s4.y, __float_as_int(is1 * id1));
        g_csredge[p2] = make_int2(s4.z, __float_as_int(is2 * id2));
        g_csredge[p3] = make_int2(s4.w, __float_as_int(is3 * id3));
    }
}

// ---------------- fused single GEMM x2 stacks (FFMA2) ----------------
__global__ void __launch_bounds__(128) gemm64_x2_kernel(const float* __restrict__ Xa,
                                                        const float* __restrict__ Wa_,
                                                        float* __restrict__ Ya,
                                                        const float* __restrict__ Xb,
                                                        const float* __restrict__ Wb_,
                                                        float* __restrict__ Yb,
                                                        int nrows, int nb) {
    __shared__ float sW[64 * 64];
    __shared__ float sX[64 * 128];
    int tid = threadIdx.x;
    int blk = blockIdx.x;
    const float* X; const float* W; float* Y;
    int rowBase;
    if (blk < nb) { X = Xa; W = Wa_; Y = Ya; rowBase = blk * 128; }
    else          { X = Xb; W = Wb_; Y = Yb; rowBase = (blk - nb) * 128; }

#pragma unroll
    for (int i = 0; i < 32; i++) sW[tid + i * 128] = W[tid + i * 128];

#pragma unroll
    for (int j = 0; j < 16; j++) {
        int idx4 = tid + j * 128;
        int r = idx4 >> 4;
        int kq = idx4 & 15;
        int grow = rowBase + r;
        float4 v = (grow < nrows) ? ((const float4*)X)[grow * 16 + kq]
                                  : make_float4(0.f, 0.f, 0.f, 0.f);
        sX[(kq * 4 + 0) * 128 + r] = v.x;
        sX[(kq * 4 + 1) * 128 + r] = v.y;
        sX[(kq * 4 + 2) * 128 + r] = v.z;
        sX[(kq * 4 + 3) * 128 + r] = v.w;
    }
    __syncthreads();

    int tx = tid & 7, ty = tid >> 3;
    int c0 = tx * 8, r0 = ty * 8;
    unsigned long long acc2[8][4];
#pragma unroll
    for (int i = 0; i < 8; i++)
#pragma unroll
        for (int j = 0; j < 4; j++) acc2[i][j] = 0ull;

#pragma unroll 8
    for (int k = 0; k < 64; k++) {
        ulonglong2 wa = *(const ulonglong2*)&sW[k * 64 + c0];       // cols (c0,c0+1),(c0+2,c0+3)
        ulonglong2 wb = *(const ulonglong2*)&sW[k * 64 + c0 + 4];   // cols (c0+4..c0+7)
        float4 x0 = *(const float4*)&sX[k * 128 + r0];
        float4 x1 = *(const float4*)&sX[k * 128 + r0 + 4];
        float xs[8] = {x0.x, x0.y, x0.z, x0.w, x1.x, x1.y, x1.z, x1.w};
#pragma unroll
        for (int ri = 0; ri < 8; ri++) {
            unsigned long long xb = pack2(xs[ri], xs[ri]);
            acc2[ri][0] = fma2(wa.x, xb, acc2[ri][0]);
            acc2[ri][1] = fma2(wa.y, xb, acc2[ri][1]);
            acc2[ri][2] = fma2(wb.x, xb, acc2[ri][2]);
            acc2[ri][3] = fma2(wb.y, xb, acc2[ri][3]);
        }
    }

#pragma unroll
    for (int ri = 0; ri < 8; ri++) {
        int row = rowBase + r0 + ri;
        if (row < nrows) {
            ulonglong2 o0; o0.x = acc2[ri][0]; o0.y = acc2[ri][1];
            ulonglong2 o1; o1.x = acc2[ri][2]; o1.y = acc2[ri][3];
            *(ulonglong2*)&Y[row * 64 + c0] = o0;
            *(ulonglong2*)&Y[row * 64 + c0 + 4] = o1;
        }
    }
}

// ---------------- fused dual GEMM x2 stacks (FFMA2) ----------------
__global__ void __launch_bounds__(256) gemm64_dual_x2_kernel(
        const float* __restrict__ X1, const float* __restrict__ W1a,
        const float* __restrict__ W1b, float* __restrict__ Y1a, float* __restrict__ Y1b,
        const float* __restrict__ X2, const float* __restrict__ W2a,
        const float* __restrict__ W2b, float* __restrict__ Y2a, float* __restrict__ Y2b,
        int nrows, int nb) {
    __shared__ float sW[64 * 128];
    __shared__ float sX[64 * 128];
    int tid = threadIdx.x;
    int blk = blockIdx.x;
    const float *X, *Wa, *Wb; float *Ya, *Yb;
    int rowBase;
    if (blk < nb) { X = X1; Wa = W1a; Wb = W1b; Ya = Y1a; Yb = Y1b; rowBase = blk * 128; }
    else          { X = X2; Wa = W2a; Wb = W2b; Ya = Y2a; Yb = Y2b; rowBase = (blk - nb) * 128; }

#pragma unroll
    for (int i = tid; i < 4096; i += 256) {
        int k = i >> 6, c = i & 63;
        sW[k * 128 + c] = Wa[i];
        sW[k * 128 + 64 + c] = Wb[i];
    }
#pragma unroll
    for (int j = 0; j < 8; j++) {
        int idx4 = tid + j * 256;
        int r = idx4 >> 4;
        int kq = idx4 & 15;
        int grow = rowBase + r;
        float4 v = (grow < nrows) ? ((const float4*)X)[grow * 16 + kq]
                                  : make_float4(0.f, 0.f, 0.f, 0.f);
        sX[(kq * 4 + 0) * 128 + r] = v.x;
        sX[(kq * 4 + 1) * 128 + r] = v.y;
        sX[(kq * 4 + 2) * 128 + r] = v.z;
        sX[(kq * 4 + 3) * 128 + r] = v.w;
    }
    __syncthreads();

    int tx = tid & 15, ty = tid >> 4;
    int c0 = tx * 8, r0 = ty * 8;
    unsigned long long acc2[8][4];
#pragma unroll
    for (int i = 0; i < 8; i++)
#pragma unroll
        for (int j = 0; j < 4; j++) acc2[i][j] = 0ull;

#pragma unroll 4
    for (int k = 0; k < 64; k++) {
        ulonglong2 wa = *(const ulonglong2*)&sW[k * 128 + c0];
        ulonglong2 wb = *(const ulonglong2*)&sW[k * 128 + c0 + 4];
        float4 x0 = *(const float4*)&sX[k * 128 + r0];
        float4 x1 = *(const float4*)&sX[k * 128 + r0 + 4];
        float xs[8] = {x0.x, x0.y, x0.z, x0.w, x1.x, x1.y, x1.z, x1.w};
#pragma unroll
        for (int ri = 0; ri < 8; ri++) {
            unsigned long long xb = pack2(xs[ri], xs[ri]);
            acc2[ri][0] = fma2(wa.x, xb, acc2[ri][0]);
            acc2[ri][1] = fma2(wa.y, xb, acc2[ri][1]);
            acc2[ri][2] = fma2(wb.x, xb, acc2[ri][2]);
            acc2[ri][3] = fma2(wb.y, xb, acc2[ri][3]);
        }
    }

    float* Yout = (c0 < 64) ? Ya : Yb;
    int cc = (c0 < 64) ? c0 : (c0 - 64);
#pragma unroll
    for (int ri = 0; ri < 8; ri++) {
        int row = rowBase + r0 + ri;
        if (row < nrows) {
            ulonglong2 o0; o0.x = acc2[ri][0]; o0.y = acc2[ri][1];
            ulonglong2 o1; o1.x = acc2[ri][2]; o1.y = acc2[ri][3];
            *(ulonglong2*)&Yout[row * 64 + cc] = o0;
            *(ulonglong2*)&Yout[row * 64 + cc + 4] = o1;
        }
    }
}

// ---------------- propagation: BOTH stacks per edge, unroll-4 ----------------
#define EDGE_FMA(e, va, vb)                                                        \
    {                                                                              \
        float nm = __int_as_float(e.y);                                            \
        acca.x = fmaf(nm, va.x, acca.x); acca.y = fmaf(nm, va.y, acca.y);          \
        acca.z = fmaf(nm, va.z, acca.z); acca.w = fmaf(nm, va.w, acca.w);          \
        accb.x = fmaf(nm, vb.x, accb.x); accb.y = fmaf(nm, vb.y, accb.y);          \
        accb.z = fmaf(nm, vb.z, accb.z); accb.w = fmaf(nm, vb.w, accb.w);          \
    }

__global__ void __launch_bounds__(256) prop_both_kernel(
        const float* __restrict__ Ta, const float* __restrict__ biasa,
        const float* __restrict__ adda, const float* __restrict__ addba,
        float* __restrict__ Houta,
        const float* __restrict__ Tb, const float* __restrict__ biasb,
        const float* __restrict__ addb, const float* __restrict__ addbb,
        float* __restrict__ Houtb, int relu_add) {
    int lane = threadIdx.x & 31;
    int warp = threadIdx.x >> 5;
    int q = lane & 15;
    int node = (blockIdx.x * 8 + warp) * 2 + (lane >> 4);
    if (node >= N_NODES) return;

    const float4* Ta4 = (const float4*)Ta;
    const float4* Tb4 = (const float4*)Tb;
    int2 oc = g_offcnt[node];
    int s0 = oc.x, s1 = oc.x + oc.y;
    float4 acca = make_float4(0.f, 0.f, 0.f, 0.f);
    float4 accb = make_float4(0.f, 0.f, 0.f, 0.f);

    int s = s0;
    for (; s + 4 <= s1; s += 4) {
        int2 e0 = g_csredge[s];
        int2 e1 = g_csredge[s + 1];
        int2 e2 = g_csredge[s + 2];
        int2 e3 = g_csredge[s + 3];
        float4 va0 = Ta4[e0.x * 16 + q], vb0 = Tb4[e0.x * 16 + q];
        float4 va1 = Ta4[e1.x * 16 + q], vb1 = Tb4[e1.x * 16 + q];
        float4 va2 = Ta4[e2.x * 16 + q], vb2 = Tb4[e2.x * 16 + q];
        float4 va3 = Ta4[e3.x * 16 + q], vb3 = Tb4[e3.x * 16 + q];
        EDGE_FMA(e0, va0, vb0);
        EDGE_FMA(e1, va1, vb1);
        EDGE_FMA(e2, va2, vb2);
        EDGE_FMA(e3, va3, vb3);
    }
    for (; s < s1; s++) {
        int2 e0 = g_csredge[s];
        float4 va0 = Ta4[e0.x * 16 + q], vb0 = Tb4[e0.x * 16 + q];
        EDGE_FMA(e0, va0, vb0);
    }

    float dv = g_dinv[node];
    float sn = dv * dv;
    // stack A combine
    {
        float4 tv = Ta4[node * 16 + q];
        float4 bv = ((const float4*)biasa)[q];
        float4 g;
        g.x = fmaxf(fmaf(sn, tv.x, acca.x) + bv.x, 0.f);
        g.y = fmaxf(fmaf(sn, tv.y, acca.y) + bv.y, 0.f);
        g.z = fmaxf(fmaf(sn, tv.z, acca.z) + bv.z, 0.f);
        g.w = fmaxf(fmaf(sn, tv.w, acca.w) + bv.w, 0.f);
        float4 av = ((const float4*)adda)[node * 16 + q];
        if (relu_add) {
            float4 ab = ((const float4*)addba)[q];
            av.x = fmaxf(av.x + ab.x, 0.f);
            av.y = fmaxf(av.y + ab.y, 0.f);
            av.z = fmaxf(av.z + ab.z, 0.f);
            av.w = fmaxf(av.w + ab.w, 0.f);
        }
        ((float4*)Houta)[node * 16 + q] =
            make_float4(g.x + av.x, g.y + av.y, g.z + av.z, g.w + av.w);
    }
    // stack B combine
    {
        float4 tv = Tb4[node * 16 + q];
        float4 bv = ((const float4*)biasb)[q];
        float4 g;
        g.x = fmaxf(fmaf(sn, tv.x, accb.x) + bv.x, 0.f);
        g.y = fmaxf(fmaf(sn, tv.y, accb.y) + bv.y, 0.f);
        g.z = fmaxf(fmaf(sn, tv.z, accb.z) + bv.z, 0.f);
        g.w = fmaxf(fmaf(sn, tv.w, accb.w) + bv.w, 0.f);
        float4 av = ((const float4*)addb)[node * 16 + q];
        if (relu_add) {
            float4 ab = ((const float4*)addbb)[q];
            av.x = fmaxf(av.x + ab.x, 0.f);
            av.y = fmaxf(av.y + ab.y, 0.f);
            av.z = fmaxf(av.z + ab.z, 0.f);
            av.w = fmaxf(av.w + ab.w, 0.f);
        }
        ((float4*)Houtb)[node * 16 + q] =
            make_float4(g.x + av.x, g.y + av.y, g.z + av.z, g.w + av.w);
    }
}

// ---------------- mean pool over sorted batch ----------------
__global__ void pool_kernel(const int* __restrict__ batch) {
    int tid = threadIdx.x;
    int c = tid & 63;
    int grp = tid >> 6;
    int base = blockIdx.x * 128;
    float acc = 0.f, cntacc = 0.f;
    int curb = -1;
    for (int j = 0; j < 32; j++) {
        int n = base + grp + j * 4;
        if (n >= N_NODES) break;
        int b = batch[n];
        if (b != curb) {
            if (curb >= 0) {
                atomicAdd(&g_psum[curb * CH + c], acc);
                if (c == 0) atomicAdd(&g_pcnt[curb], cntacc);
            }
            curb = b; acc = 0.f; cntacc = 0.f;
        }
        acc += g_H[n * CH + c] + g_HS[n * CH + c];
        cntacc += 1.0f;
    }
    if (curb >= 0) {
        atomicAdd(&g_psum[curb * CH + c], acc);
        if (c == 0) atomicAdd(&g_pcnt[curb], cntacc);
    }
}

// ---------------- final readout ----------------
__global__ void final_kernel(const float* __restrict__ Wf, const float* __restrict__ bf,
                             float* __restrict__ out) {
    int g = threadIdx.x;
    if (g >= N_GRAPHS) return;
    float inv = 1.0f / fmaxf(g_pcnt[g], 1.0f);
    float s = 0.f;
#pragma unroll
    for (int c = 0; c < CH; c++) s += (g_psum[g * CH + c] * inv) * Wf[c];
    out[g] = s + bf[0];
}

// ---------------- launch ----------------
extern "C" void kernel_launch(void* const* d_in, const int* in_sizes, int n_in,
                              void* d_out, int out_size) {
    const float* x    = (const float*)d_in[0];
    const float* xsc  = (const float*)d_in[1];
    const float* W1   = (const float*)d_in[2];
    const float* b1   = (const float*)d_in[3];
    const float* W2   = (const float*)d_in[4];
    const float* b2   = (const float*)d_in[5];
    const float* We   = (const float*)d_in[6];
    const float* be   = (const float*)d_in[7];
    const float* W1s  = (const float*)d_in[8];
    const float* b1s  = (const float*)d_in[9];
    const float* W2s  = (const float*)d_in[10];
    const float* b2s  = (const float*)d_in[11];
    const float* Wes  = (const float*)d_in[12];
    const float* bes  = (const float*)d_in[13];
    const float* Wf   = (const float*)d_in[14];
    const float* bf   = (const float*)d_in[15];
    const int*   ei   = (const int*)d_in[16];
    const int*   batch = (const int*)d_in[17];
    float* out = (float*)d_out;

    const int* e_src = ei;
    const int* e_dst = ei + N_EDGES;

    float *T, *S, *T2, *S2, *H, *HS;
    cudaGetSymbolAddress((void**)&T, g_T);
    cudaGetSymbolAddress((void**)&S, g_S);
    cudaGetSymbolAddress((void**)&T2, g_T2);
    cudaGetSymbolAddress((void**)&S2, g_S2);
    cudaGetSymbolAddress((void**)&H, g_H);
    cudaGetSymbolAddress((void**)&HS, g_HS);

    int e4grid = (N_EDGES / 4 + 255) / 256;             // 782 blocks (4 edges/thread)
    int nb = (N_NODES + 127) / 128;                     // 391 blocks per stack
    int pgrid = (N_NODES + 15) / 16;                    // both-stack prop: 3125 blocks

    // graph structure (4 launches, down from 6)
    zero_kernel<<<(N_NODES + 255) / 256, 256>>>();
    hist_kernel<<<e4grid, 256>>>(e_dst);
    scan_fused_kernel<<<SCAN_BLOCKS, 256>>>();
    fill_kernel<<<e4grid, 256>>>(e_src, e_dst);

    // layer 1: T=x@W1, S=x@We | T2=xsc@W1s, S2=xsc@Wes (fused both stacks)
    gemm64_dual_x2_kernel<<<2 * nb, 256>>>(x, W1, We, T, S,
                                           xsc, W1s, Wes, T2, S2, N_NODES, nb);
    // prop layer 1 (both stacks per edge)
    prop_both_kernel<<<pgrid, 256>>>(T, b1, S, be, H,
                                     T2, b1s, S2, bes, HS, 1);
    // layer 2 GEMM: T=H@W2 | T2=HS@W2s
    gemm64_x2_kernel<<<2 * nb, 128>>>(H, W2, T, HS, W2s, T2, N_NODES, nb);
    // prop layer 2 (both stacks per edge)
    prop_both_kernel<<<pgrid, 256>>>(T, b2, H, nullptr, H,
                                     T2, b2s, HS, nullptr, HS, 0);

    // pool + readout
    pool_kernel<<<(N_NODES + 127) / 128, 256>>>(batch);
    final_kernel<<<1, 64>>>(Wf, bf, out);
}

// round 15
// speedup vs baseline: 1.8085x; 1.0840x over previous
#include <cuda_runtime.h>
#include <cuda_bf16.h>
#include <cuda_fp16.h>

#define N_NODES 50000
#define N_EDGES 800000
#define N_GRAPHS 64
#define CH 64
#define SCAN_BLOCKS 196   // 196*256 = 50176 >= N_NODES

// ---------------- packed f32x2 helpers (sm_103a FFMA2 path) ----------------
__device__ __forceinline__ unsigned long long fma2(unsigned long long a,
                                                   unsigned long long b,
                                                   unsigned long long c) {
    unsigned long long d;
    asm("fma.rn.f32x2 %0, %1, %2, %3;" : "=l"(d) : "l"(a), "l"(b), "l"(c));
    return d;
}
__device__ __forceinline__ unsigned long long pack2(float x, float y) {
    unsigned long long r;
    asm("mov.b64 %0, {%1, %2};" : "=l"(r) : "f"(x), "f"(y));
    return r;
}
__device__ __forceinline__ float2 unpack2(unsigned long long v) {
    float2 r;
    asm("mov.b64 {%0, %1}, %2;" : "=f"(r.x), "=f"(r.y) : "l"(v));
    return r;
}
// 4 packed-f32x2 accumulators (8 floats) -> 8 halves as uint4
__device__ __forceinline__ uint4 acc_to_half8(unsigned long long a0, unsigned long long a1,
                                              unsigned long long a2, unsigned long long a3) {
    float2 f0 = unpack2(a0), f1 = unpack2(a1), f2 = unpack2(a2), f3 = unpack2(a3);
    __half2 h[4];
    h[0] = __floats2half2_rn(f0.x, f0.y);
    h[1] = __floats2half2_rn(f1.x, f1.y);
    h[2] = __floats2half2_rn(f2.x, f2.y);
    h[3] = __floats2half2_rn(f3.x, f3.y);
    return *reinterpret_cast<uint4*>(h);
}
// 4 halves (uint2) -> float4
__device__ __forceinline__ float4 h4_to_f4(uint2 u) {
    __half2 a = *reinterpret_cast<__half2*>(&u.x);
    __half2 b = *reinterpret_cast<__half2*>(&u.y);
    float2 fa = __half22float2(a), fb = __half22float2(b);
    return make_float4(fa.x, fa.y, fb.x, fb.y);
}

// ---------------- scratch (static device globals; no allocation) ----------------
__device__ __half g_T[N_NODES * CH];     // stack-1 gcn pre-act (fp16, gathered)
__device__ __half g_T2[N_NODES * CH];    // stack-2 gcn pre-act (fp16, gathered)
__device__ float g_S[N_NODES * CH];      // stack-1 skip pre-act (fp32)
__device__ float g_S2[N_NODES * CH];     // stack-2 skip pre-act (fp32)
__device__ float g_H[N_NODES * CH];      // stack-1 state (fp32)
__device__ float g_HS[N_NODES * CH];     // stack-2 state (fp32)
__device__ float g_dinv[N_NODES];
__device__ int   g_cnt[N_NODES];         // zero at module load; re-zeroed by scan each replay
__device__ int2  g_offcnt[N_NODES];      // {bucket offset, count}
__device__ int   g_cursor[N_NODES];
__device__ int   g_counter;              // zero at load; reset by fill thread 0 each replay
__device__ int2  g_csredge[N_EDGES];     // {src, __float_as_int(norm)} packed
__device__ float g_psum[N_GRAPHS * CH];  // zero at load; re-zeroed by final each replay
__device__ float g_pcnt[N_GRAPHS];

// ---------------- degree histogram, 4 edges/thread (int4 loads) ----------------
__global__ void hist_kernel(const int* __restrict__ dst) {
    int t = blockIdx.x * blockDim.x + threadIdx.x;
    if (t * 4 < N_EDGES) {
        int4 d = ((const int4*)dst)[t];
        atomicAdd(&g_cnt[d.x], 1);
        atomicAdd(&g_cnt[d.y], 1);
        atomicAdd(&g_cnt[d.z], 1);
        atomicAdd(&g_cnt[d.w], 1);
    }
}

// ---------------- fused single-kernel scan: atomic block-base allocation ----------------
// Also re-zeroes g_cnt for the next replay (deterministic: zero at load, zeroed here each pass).
__global__ void scan_fused_kernel() {
    __shared__ int sh[256];
    __shared__ int base_sh;
    int tid = threadIdx.x;
    int i = blockIdx.x * 256 + tid;
    int c = (i < N_NODES) ? g_cnt[i] : 0;
    sh[tid] = c;
    __syncthreads();
    for (int d = 1; d < 256; d <<= 1) {
        int t = (tid >= d) ? sh[tid - d] : 0;
        __syncthreads();
        sh[tid] += t;
        __syncthreads();
    }
    if (tid == 0) base_sh = atomicAdd(&g_counter, sh[255]);
    __syncthreads();
    if (i < N_NODES) {
        int off = base_sh + sh[tid] - c;
        g_offcnt[i] = make_int2(off, c);
        g_cursor[i] = off;
        g_dinv[i] = rsqrtf(1.0f + (float)c);
        g_cnt[i] = 0;                      // reset for next replay's hist
    }
}

// ---------------- CSR fill: 4 edges/thread, packed STG.64 ----------------
__global__ void fill_kernel(const int* __restrict__ src, const int* __restrict__ dst) {
    int t = blockIdx.x * blockDim.x + threadIdx.x;
    if (t == 0) g_counter = 0;             // reset bucket allocator for next replay's scan
    if (t * 4 < N_EDGES) {
        int4 s4 = ((const int4*)src)[t];
        int4 d4 = ((const int4*)dst)[t];
        float is0 = g_dinv[s4.x], id0 = g_dinv[d4.x];
        float is1 = g_dinv[s4.y], id1 = g_dinv[d4.y];
        float is2 = g_dinv[s4.z], id2 = g_dinv[d4.z];
        float is3 = g_dinv[s4.w], id3 = g_dinv[d4.w];
        int p0 = atomicAdd(&g_cursor[d4.x], 1);
        int p1 = atomicAdd(&g_cursor[d4.y], 1);
        int p2 = atomicAdd(&g_cursor[d4.z], 1);
        int p3 = atomicAdd(&g_cursor[d4.w], 1);
        g_csredge[p0] = make_int2(s4.x, __float_as_int(is0 * id0));
        g_csredge[p1] = make_int2(s4.y, __float_as_int(is1 * id1));
        g_csredge[p2] = make_int2(s4.z, __float_as_int(is2 * id2));
        g_csredge[p3] = make_int2(s4.w, __float_as_int(is3 * id3));
    }
}

// ---------------- fused single GEMM x2 stacks (FFMA2, fp16 output) ----------------
__global__ void __launch_bounds__(128) gemm64_x2_kernel(const float* __restrict__ Xa,
                                                        const float* __restrict__ Wa_,
                                                        __half* __restrict__ Ya,
                                                        const float* __restrict__ Xb,
                                                        const float* __restrict__ Wb_,
                                                        __half* __restrict__ Yb,
                                                        int nrows, int nb) {
    __shared__ float sW[64 * 64];
    __shared__ float sX[64 * 128];
    int tid = threadIdx.x;
    int blk = blockIdx.x;
    const float* X; const float* W; __half* Y;
    int rowBase;
    if (blk < nb) { X = Xa; W = Wa_; Y = Ya; rowBase = blk * 128; }
    else          { X = Xb; W = Wb_; Y = Yb; rowBase = (blk - nb) * 128; }

#pragma unroll
    for (int i = 0; i < 32; i++) sW[tid + i * 128] = W[tid + i * 128];

#pragma unroll
    for (int j = 0; j < 16; j++) {
        int idx4 = tid + j * 128;
        int r = idx4 >> 4;
        int kq = idx4 & 15;
        int grow = rowBase + r;
        float4 v = (grow < nrows) ? ((const float4*)X)[grow * 16 + kq]
                                  : make_float4(0.f, 0.f, 0.f, 0.f);
        sX[(kq * 4 + 0) * 128 + r] = v.x;
        sX[(kq * 4 + 1) * 128 + r] = v.y;
        sX[(kq * 4 + 2) * 128 + r] = v.z;
        sX[(kq * 4 + 3) * 128 + r] = v.w;
    }
    __syncthreads();

    int tx = tid & 7, ty = tid >> 3;
    int c0 = tx * 8, r0 = ty * 8;
    unsigned long long acc2[8][4];
#pragma unroll
    for (int i = 0; i < 8; i++)
#pragma unroll
        for (int j = 0; j < 4; j++) acc2[i][j] = 0ull;

#pragma unroll 8
    for (int k = 0; k < 64; k++) {
        ulonglong2 wa = *(const ulonglong2*)&sW[k * 64 + c0];
        ulonglong2 wb = *(const ulonglong2*)&sW[k * 64 + c0 + 4];
        float4 x0 = *(const float4*)&sX[k * 128 + r0];
        float4 x1 = *(const float4*)&sX[k * 128 + r0 + 4];
        float xs[8] = {x0.x, x0.y, x0.z, x0.w, x1.x, x1.y, x1.z, x1.w};
#pragma unroll
        for (int ri = 0; ri < 8; ri++) {
            unsigned long long xb = pack2(xs[ri], xs[ri]);
            acc2[ri][0] = fma2(wa.x, xb, acc2[ri][0]);
            acc2[ri][1] = fma2(wa.y, xb, acc2[ri][1]);
            acc2[ri][2] = fma2(wb.x, xb, acc2[ri][2]);
            acc2[ri][3] = fma2(wb.y, xb, acc2[ri][3]);
        }
    }

#pragma unroll
    for (int ri = 0; ri < 8; ri++) {
        int row = rowBase + r0 + ri;
        if (row < nrows) {
            uint4 h8 = acc_to_half8(acc2[ri][0], acc2[ri][1], acc2[ri][2], acc2[ri][3]);
            *(uint4*)&Y[row * 64 + c0] = h8;     // 16B aligned: c0 % 8 == 0
        }
    }
}

// ---------------- fused dual GEMM x2 stacks (FFMA2; T half, S fp32) ----------------
__global__ void __launch_bounds__(256) gemm64_dual_x2_kernel(
        const float* __restrict__ X1, const float* __restrict__ W1a,
        const float* __restrict__ W1b, __half* __restrict__ Y1a, float* __restrict__ Y1b,
        const float* __restrict__ X2, const float* __restrict__ W2a,
        const float* __restrict__ W2b, __half* __restrict__ Y2a, float* __restrict__ Y2b,
        int nrows, int nb) {
    __shared__ float sW[64 * 128];
    __shared__ float sX[64 * 128];
    int tid = threadIdx.x;
    int blk = blockIdx.x;
    const float *X, *Wa, *Wb; __half* Ya; float* Yb;
    int rowBase;
    if (blk < nb) { X = X1; Wa = W1a; Wb = W1b; Ya = Y1a; Yb = Y1b; rowBase = blk * 128; }
    else          { X = X2; Wa = W2a; Wb = W2b; Ya = Y2a; Yb = Y2b; rowBase = (blk - nb) * 128; }

#pragma unroll
    for (int i = tid; i < 4096; i += 256) {
        int k = i >> 6, c = i & 63;
        sW[k * 128 + c] = Wa[i];
        sW[k * 128 + 64 + c] = Wb[i];
    }
#pragma unroll
    for (int j = 0; j < 8; j++) {
        int idx4 = tid + j * 256;
        int r = idx4 >> 4;
        int kq = idx4 & 15;
        int grow = rowBase + r;
        float4 v = (grow < nrows) ? ((const float4*)X)[grow * 16 + kq]
                                  : make_float4(0.f, 0.f, 0.f, 0.f);
        sX[(kq * 4 + 0) * 128 + r] = v.x;
        sX[(kq * 4 + 1) * 128 + r] = v.y;
        sX[(kq * 4 + 2) * 128 + r] = v.z;
        sX[(kq * 4 + 3) * 128 + r] = v.w;
    }
    __syncthreads();

    int tx = tid & 15, ty = tid >> 4;
    int c0 = tx * 8, r0 = ty * 8;
    unsigned long long acc2[8][4];
#pragma unroll
    for (int i = 0; i < 8; i++)
#pragma unroll
        for (int j = 0; j < 4; j++) acc2[i][j] = 0ull;

#pragma unroll 4
    for (int k = 0; k < 64; k++) {
        ulonglong2 wa = *(const ulonglong2*)&sW[k * 128 + c0];
        ulonglong2 wb = *(const ulonglong2*)&sW[k * 128 + c0 + 4];
        float4 x0 = *(const float4*)&sX[k * 128 + r0];
        float4 x1 = *(const float4*)&sX[k * 128 + r0 + 4];
        float xs[8] = {x0.x, x0.y, x0.z, x0.w, x1.x, x1.y, x1.z, x1.w};
#pragma unroll
        for (int ri = 0; ri < 8; ri++) {
            unsigned long long xb = pack2(xs[ri], xs[ri]);
            acc2[ri][0] = fma2(wa.x, xb, acc2[ri][0]);
            acc2[ri][1] = fma2(wa.y, xb, acc2[ri][1]);
            acc2[ri][2] = fma2(wb.x, xb, acc2[ri][2]);
            acc2[ri][3] = fma2(wb.y, xb, acc2[ri][3]);
        }
    }

#pragma unroll
    for (int ri = 0; ri < 8; ri++) {
        int row = rowBase + r0 + ri;
        if (row < nrows) {
            if (c0 < 64) {     // T path: fp16
                uint4 h8 = acc_to_half8(acc2[ri][0], acc2[ri][1], acc2[ri][2], acc2[ri][3]);
                *(uint4*)&Ya[row * 64 + c0] = h8;
            } else {           // S path: fp32
                int cc = c0 - 64;
                ulonglong2 o0; o0.x = acc2[ri][0]; o0.y = acc2[ri][1];
                ulonglong2 o1; o1.x = acc2[ri][2]; o1.y = acc2[ri][3];
                *(ulonglong2*)&Yb[row * 64 + cc] = o0;
                *(ulonglong2*)&Yb[row * 64 + cc + 4] = o1;
            }
        }
    }
}

// ---------------- propagation: BOTH stacks per edge, fp16 gathers, unroll-4 ----------------
#define EDGE_FMA_H(e, ua, ub)                                                      \
    {                                                                              \
        float nm = __int_as_float(e.y);                                            \
        float4 va = h4_to_f4(ua);                                                  \
        float4 vb = h4_to_f4(ub);                                                  \
        acca.x = fmaf(nm, va.x, acca.x); acca.y = fmaf(nm, va.y, acca.y);          \
        acca.z = fmaf(nm, va.z, acca.z); acca.w = fmaf(nm, va.w, acca.w);          \
        accb.x = fmaf(nm, vb.x, accb.x); accb.y = fmaf(nm, vb.y, accb.y);          \
        accb.z = fmaf(nm, vb.z, accb.z); accb.w = fmaf(nm, vb.w, accb.w);          \
    }

__global__ void __launch_bounds__(256) prop_both_kernel(
        const __half* __restrict__ Ta, const float* __restrict__ biasa,
        const float* __restrict__ adda, const float* __restrict__ addba,
        float* __restrict__ Houta,
        const __half* __restrict__ Tb, const float* __restrict__ biasb,
        const float* __restrict__ addb, const float* __restrict__ addbb,
        float* __restrict__ Houtb, int relu_add) {
    int lane = threadIdx.x & 31;
    int warp = threadIdx.x >> 5;
    int q = lane & 15;                      // uint2 index: channels q*4..q*4+3
    int node = (blockIdx.x * 8 + warp) * 2 + (lane >> 4);
    if (node >= N_NODES) return;

    const uint2* Ta8 = (const uint2*)Ta;    // row = 16 x uint2 (64 halves = 128B)
    const uint2* Tb8 = (const uint2*)Tb;
    int2 oc = g_offcnt[node];
    int s0 = oc.x, s1 = oc.x + oc.y;
    float4 acca = make_float4(0.f, 0.f, 0.f, 0.f);
    float4 accb = make_float4(0.f, 0.f, 0.f, 0.f);

    int s = s0;
    for (; s + 4 <= s1; s += 4) {
        int2 e0 = g_csredge[s];
        int2 e1 = g_csredge[s + 1];
        int2 e2 = g_csredge[s + 2];
        int2 e3 = g_csredge[s + 3];
        uint2 ua0 = Ta8[e0.x * 16 + q], ub0 = Tb8[e0.x * 16 + q];
        uint2 ua1 = Ta8[e1.x * 16 + q], ub1 = Tb8[e1.x * 16 + q];
        uint2 ua2 = Ta8[e2.x * 16 + q], ub2 = Tb8[e2.x * 16 + q];
        uint2 ua3 = Ta8[e3.x * 16 + q], ub3 = Tb8[e3.x * 16 + q];
        EDGE_FMA_H(e0, ua0, ub0);
        EDGE_FMA_H(e1, ua1, ub1);
        EDGE_FMA_H(e2, ua2, ub2);
        EDGE_FMA_H(e3, ua3, ub3);
    }
    for (; s < s1; s++) {
        int2 e0 = g_csredge[s];
        uint2 ua0 = Ta8[e0.x * 16 + q], ub0 = Tb8[e0.x * 16 + q];
        EDGE_FMA_H(e0, ua0, ub0);
    }

    float dv = g_dinv[node];
    float sn = dv * dv;
    // stack A combine
    {
        float4 tv = h4_to_f4(Ta8[node * 16 + q]);
        float4 bv = ((const float4*)biasa)[q];
        float4 g;
        g.x = fmaxf(fmaf(sn, tv.x, acca.x) + bv.x, 0.f);
        g.y = fmaxf(fmaf(sn, tv.y, acca.y) + bv.y, 0.f);
        g.z = fmaxf(fmaf(sn, tv.z, acca.z) + bv.z, 0.f);
        g.w = fmaxf(fmaf(sn, tv.w, acca.w) + bv.w, 0.f);
        float4 av = ((const float4*)adda)[node * 16 + q];
        if (relu_add) {
            float4 ab = ((const float4*)addba)[q];
            av.x = fmaxf(av.x + ab.x, 0.f);
            av.y = fmaxf(av.y + ab.y, 0.f);
            av.z = fmaxf(av.z + ab.z, 0.f);
            av.w = fmaxf(av.w + ab.w, 0.f);
        }
        ((float4*)Houta)[node * 16 + q] =
            make_float4(g.x + av.x, g.y + av.y, g.z + av.z, g.w + av.w);
    }
    // stack B combine
    {
        float4 tv = h4_to_f4(Tb8[node * 16 + q]);
        float4 bv = ((const float4*)biasb)[q];
        float4 g;
        g.x = fmaxf(fmaf(sn, tv.x, accb.x) + bv.x, 0.f);
        g.y = fmaxf(fmaf(sn, tv.y, accb.y) + bv.y, 0.f);
        g.z = fmaxf(fmaf(sn, tv.z, accb.z) + bv.z, 0.f);
        g.w = fmaxf(fmaf(sn, tv.w, accb.w) + bv.w, 0.f);
        float4 av = ((const float4*)addb)[node * 16 + q];
        if (relu_add) {
            float4 ab = ((const float4*)addbb)[q];
            av.x = fmaxf(av.x + ab.x, 0.f);
            av.y = fmaxf(av.y + ab.y, 0.f);
            av.z = fmaxf(av.z + ab.z, 0.f);
            av.w = fmaxf(av.w + ab.w, 0.f);
        }
        ((float4*)Houtb)[node * 16 + q] =
            make_float4(g.x + av.x, g.y + av.y, g.z + av.z, g.w + av.w);
    }
}

// ---------------- mean pool over sorted batch ----------------
__global__ void pool_kernel(const int* __restrict__ batch) {
    int tid = threadIdx.x;
    int c = tid & 63;
    int grp = tid >> 6;
    int base = blockIdx.x * 128;
    float acc = 0.f, cntacc = 0.f;
    int curb = -1;
    for (int j = 0; j < 32; j++) {
        int n = base + grp + j * 4;
        if (n >= N_NODES) break;
        int b = batch[n];
        if (b != curb) {
            if (curb >= 0) {
                atomicAdd(&g_psum[curb * CH + c], acc);
                if (c == 0) atomicAdd(&g_pcnt[curb], cntacc);
            }
            curb = b; acc = 0.f; cntacc = 0.f;
        }
        acc += g_H[n * CH + c] + g_HS[n * CH + c];
        cntacc += 1.0f;
    }
    if (curb >= 0) {
        atomicAdd(&g_psum[curb * CH + c], acc);
        if (c == 0) atomicAdd(&g_pcnt[curb], cntacc);
    }
}

// ---------------- final readout (also re-zeroes psum/pcnt for next replay) ----------------
__global__ void final_kernel(const float* __restrict__ Wf, const float* __restrict__ bf,
                             float* __restrict__ out) {
    int g = threadIdx.x;
    if (g >= N_GRAPHS) return;
    float inv = 1.0f / fmaxf(g_pcnt[g], 1.0f);
    float s = 0.f;
#pragma unroll
    for (int c = 0; c < CH; c++) {
        s += (g_psum[g * CH + c] * inv) * Wf[c];
        g_psum[g * CH + c] = 0.f;        // reset for next replay's pool
    }
    g_pcnt[g] = 0.f;
    out[g] = s + bf[0];
}

// ---------------- launch ----------------
extern "C" void kernel_launch(void* const* d_in, const int* in_sizes, int n_in,
                              void* d_out, int out_size) {
    const float* x    = (const float*)d_in[0];
    const float* xsc  = (const float*)d_in[1];
    const float* W1   = (const float*)d_in[2];
    const float* b1   = (const float*)d_in[3];
    const float* W2   = (const float*)d_in[4];
    const float* b2   = (const float*)d_in[5];
    const float* We   = (const float*)d_in[6];
    const float* be   = (const float*)d_in[7];
    const float* W1s  = (const float*)d_in[8];
    const float* b1s  = (const float*)d_in[9];
    const float* W2s  = (const float*)d_in[10];
    const float* b2s  = (const float*)d_in[11];
    const float* Wes  = (const float*)d_in[12];
    const float* bes  = (const float*)d_in[13];
    const float* Wf   = (const float*)d_in[14];
    const float* bf   = (const float*)d_in[15];
    const int*   ei   = (const int*)d_in[16];
    const int*   batch = (const int*)d_in[17];
    float* out = (float*)d_out;

    const int* e_src = ei;
    const int* e_dst = ei + N_EDGES;

    __half *T, *T2;
    float *S, *S2, *H, *HS;
    cudaGetSymbolAddress((void**)&T, g_T);
    cudaGetSymbolAddress((void**)&T2, g_T2);
    cudaGetSymbolAddress((void**)&S, g_S);
    cudaGetSymbolAddress((void**)&S2, g_S2);
    cudaGetSymbolAddress((void**)&H, g_H);
    cudaGetSymbolAddress((void**)&HS, g_HS);

    int e4grid = (N_EDGES / 4 + 255) / 256;             // 782 blocks
    int nb = (N_NODES + 127) / 128;                     // 391 blocks per stack
    int pgrid = (N_NODES + 15) / 16;                    // both-stack prop: 3125 blocks

    // graph structure (3 launches; resets folded into kernels)
    hist_kernel<<<e4grid, 256>>>(e_dst);
    scan_fused_kernel<<<SCAN_BLOCKS, 256>>>();
    fill_kernel<<<e4grid, 256>>>(e_src, e_dst);

    // layer 1: T=x@W1 (fp16), S=x@We (fp32) | T2=xsc@W1s, S2=xsc@Wes
    gemm64_dual_x2_kernel<<<2 * nb, 256>>>(x, W1, We, T, S,
                                           xsc, W1s, Wes, T2, S2, N_NODES, nb);
    // prop layer 1 (both stacks per edge, fp16 gathers)
    prop_both_kernel<<<pgrid, 256>>>(T, b1, S, be, H,
                                     T2, b1s, S2, bes, HS, 1);
    // layer 2 GEMM: T=H@W2 (fp16) | T2=HS@W2s
    gemm64_x2_kernel<<<2 * nb, 128>>>(H, W2, T, HS, W2s, T2, N_NODES, nb);
    // prop layer 2 (both stacks per edge)
    prop_both_kernel<<<pgrid, 256>>>(T, b2, H, nullptr, H,
                                     T2, b2s, HS, nullptr, HS, 0);

    // pool + readout
    pool_kernel<<<(N_NODES + 127) / 128, 256>>>(batch);
    final_kernel<<<1, 64>>>(Wf, bf, out);
}

// round 17
// speedup vs baseline: 2.4168x; 1.3364x over previous
#include <cuda_runtime.h>
#include <cuda_bf16.h>
#include <cuda_fp16.h>
#include <cstdint>

#define N_NODES 50000
#define N_EDGES 800000
#define N_GRAPHS 64
#define CH 64
#define SCAN_BLOCKS 196   // 196*256 = 50176 >= N_NODES
#define APAD 72           // smem row stride in halves (64 + 8 pad, conflict-free fragments)

// ---------------- warp-level tensor MMA: m16n8k16 f16*f16+f32 (sm_80 PTX, works on compute_103) ----
__device__ __forceinline__ void mma16816(float* c, uint32_t a0, uint32_t a1, uint32_t a2,
                                         uint32_t a3, uint32_t b0, uint32_t b1) {
    asm volatile(
        "mma.sync.aligned.m16n8k16.row.col.f32.f16.f16.f32 "
        "{%0,%1,%2,%3}, {%4,%5,%6,%7}, {%8,%9}, {%0,%1,%2,%3};"
        : "+f"(c[0]), "+f"(c[1]), "+f"(c[2]), "+f"(c[3])
        : "r"(a0), "r"(a1), "r"(a2), "r"(a3), "r"(b0), "r"(b1));
}

// ---------------- fp16 helpers ----------------
__device__ __forceinline__ float4 h4_to_f4(uint2 u) {
    __half2 a = *reinterpret_cast<__half2*>(&u.x);
    __half2 b = *reinterpret_cast<__half2*>(&u.y);
    float2 fa = __half22float2(a), fb = __half22float2(b);
    return make_float4(fa.x, fa.y, fb.x, fb.y);
}
__device__ __forceinline__ uint4 f8_to_h8(float4 a, float4 b) {
    __half2 h[4];
    h[0] = __floats2half2_rn(a.x, a.y);
    h[1] = __floats2half2_rn(a.z, a.w);
    h[2] = __floats2half2_rn(b.x, b.y);
    h[3] = __floats2half2_rn(b.z, b.w);
    return *reinterpret_cast<uint4*>(h);
}

// ---------------- scratch (static device globals; no allocation) ----------------
__device__ __half g_T[N_NODES * CH];     // stack-1 gcn pre-act (fp16, gathered)
__device__ __half g_T2[N_NODES * CH];    // stack-2 gcn pre-act (fp16, gathered)
__device__ float g_S[N_NODES * CH];      // stack-1 skip pre-act (fp32)
__device__ float g_S2[N_NODES * CH];     // stack-2 skip pre-act (fp32)
__device__ float g_H[N_NODES * CH];      // stack-1 state (fp32)
__device__ float g_HS[N_NODES * CH];     // stack-2 state (fp32)
__device__ float g_dinv[N_NODES];
__device__ int   g_cnt[N_NODES];
__device__ int2  g_offcnt[N_NODES];
__device__ int   g_cursor[N_NODES];
__device__ int   g_counter;
__device__ int2  g_csredge[N_EDGES];
__device__ float g_psum[N_GRAPHS * CH];
__device__ float g_pcnt[N_GRAPHS];

// ---------------- degree histogram, 4 edges/thread ----------------
__global__ void hist_kernel(const int* __restrict__ dst) {
    int t = blockIdx.x * blockDim.x + threadIdx.x;
    if (t * 4 < N_EDGES) {
        int4 d = ((const int4*)dst)[t];
        atomicAdd(&g_cnt[d.x], 1);
        atomicAdd(&g_cnt[d.y], 1);
        atomicAdd(&g_cnt[d.z], 1);
        atomicAdd(&g_cnt[d.w], 1);
    }
}

// ---------------- fused scan ----------------
__global__ void scan_fused_kernel() {
    __shared__ int sh[256];
    __shared__ int base_sh;
    int tid = threadIdx.x;
    int i = blockIdx.x * 256 + tid;
    int c = (i < N_NODES) ? g_cnt[i] : 0;
    sh[tid] = c;
    __syncthreads();
    for (int d = 1; d < 256; d <<= 1) {
        int t = (tid >= d) ? sh[tid - d] : 0;
        __syncthreads();
        sh[tid] += t;
        __syncthreads();
    }
    if (tid == 0) base_sh = atomicAdd(&g_counter, sh[255]);
    __syncthreads();
    if (i < N_NODES) {
        int off = base_sh + sh[tid] - c;
        g_offcnt[i] = make_int2(off, c);
        g_cursor[i] = off;
        g_dinv[i] = rsqrtf(1.0f + (float)c);
        g_cnt[i] = 0;
    }
}

// ---------------- CSR fill ----------------
__global__ void fill_kernel(const int* __restrict__ src, const int* __restrict__ dst) {
    int t = blockIdx.x * blockDim.x + threadIdx.x;
    if (t == 0) g_counter = 0;
    if (t * 4 < N_EDGES) {
        int4 s4 = ((const int4*)src)[t];
        int4 d4 = ((const int4*)dst)[t];
        float is0 = g_dinv[s4.x], id0 = g_dinv[d4.x];
        float is1 = g_dinv[s4.y], id1 = g_dinv[d4.y];
        float is2 = g_dinv[s4.z], id2 = g_dinv[d4.z];
        float is3 = g_dinv[s4.w], id3 = g_dinv[d4.w];
        int p0 = atomicAdd(&g_cursor[d4.x], 1);
        int p1 = atomicAdd(&g_cursor[d4.y], 1);
        int p2 = atomicAdd(&g_cursor[d4.z], 1);
        int p3 = atomicAdd(&g_cursor[d4.w], 1);
        g_csredge[p0] = make_int2(s4.x, __float_as_int(is0 * id0));
        g_csredge[p1] = make_int2(s4.y, __float_as_int(is1 * id1));
        g_csredge[p2] = make_int2(s4.z, __float_as_int(is2 * id2));
        g_csredge[p3] = make_int2(s4.w, __float_as_int(is3 * id3));
    }
}

// ================= HMMA GEMM kernels =================
// sA[128][APAD] fp16 (row, k) ; sBt[N][APAD] fp16 (n, k) = W^T.
// Warp w computes rows [w*16, w*16+16), all N columns, K=64 in 4 k-tiles.

// ---- dual: N=128 ([Wa|Wb]); Ya fp16 (n 0-63), Yb fp32 (n 64-127) ----
__global__ void __launch_bounds__(256) mma_dual_x2_kernel(
        const float* __restrict__ X1, const float* __restrict__ W1a,
        const float* __restrict__ W1b, __half* __restrict__ Y1a, float* __restrict__ Y1b,
        const float* __restrict__ X2, const float* __restrict__ W2a,
        const float* __restrict__ W2b, __half* __restrict__ Y2a, float* __restrict__ Y2b,
        int nrows, int nb) {
    __shared__ __half sA[128 * APAD];    // 18KB
    __shared__ __half sBt[128 * APAD];   // 18KB
    int tid = threadIdx.x;
    int wid = tid >> 5;
    int lane = tid & 31;
    int blk = blockIdx.x;
    const float *X, *Wa, *Wb; __half* Ya; float* Yb;
    int rowBase;
    if (blk < nb) { X = X1; Wa = W1a; Wb = W1b; Ya = Y1a; Yb = Y1b; rowBase = blk * 128; }
    else          { X = X2; Wa = W2a; Wb = W2b; Ya = Y2a; Yb = Y2b; rowBase = (blk - nb) * 128; }

    // A fill: thread t -> row t&127, k-half (t>>7)*32
    {
        int r = tid & 127;
        int k0 = (tid >> 7) * 32;
        int grow = rowBase + r;
        uint4* dst = (uint4*)&sA[r * APAD + k0];
#pragma unroll
        for (int j = 0; j < 4; j++) {
            float4 a, b;
            if (grow < nrows) {
                a = ((const float4*)X)[grow * 16 + (k0 >> 2) + 2 * j];
                b = ((const float4*)X)[grow * 16 + (k0 >> 2) + 2 * j + 1];
            } else {
                a = make_float4(0.f, 0.f, 0.f, 0.f);
                b = a;
            }
            dst[j] = f8_to_h8(a, b);
        }
    }
    // Bt fill: thread t -> n = t>>1, k-half (t&1)*32 ; sBt[n][k] = W[k][n]
    {
        int n = tid >> 1;
        int k0 = (tid & 1) * 32;
        const float* Wsrc = (n < 64) ? Wa : Wb;
        int col = n & 63;
        __half2 tmp[16];
#pragma unroll
        for (int j = 0; j < 16; j++) {
            float w0 = Wsrc[(k0 + 2 * j) * 64 + col];
            float w1 = Wsrc[(k0 + 2 * j + 1) * 64 + col];
            tmp[j] = __floats2half2_rn(w0, w1);
        }
        uint4* dst = (uint4*)&sBt[n * APAD + k0];
#pragma unroll
        for (int j = 0; j < 4; j++) dst[j] = ((uint4*)tmp)[j];
    }
    __syncthreads();

    // MMA mainloop
    float acc[16][4];
#pragma unroll
    for (int i = 0; i < 16; i++)
#pragma unroll
        for (int j = 0; j < 4; j++) acc[i][j] = 0.f;

    int r0 = wid * 16;
    int fr = lane >> 2;          // fragment row 0-7
    int fq = (lane & 3) * 2;     // fragment k-pair offset
#pragma unroll
    for (int kt = 0; kt < 4; kt++) {
        const __half* pa = &sA[(r0 + fr) * APAD + kt * 16 + fq];
        uint32_t a0 = *(const uint32_t*)pa;
        uint32_t a1 = *(const uint32_t*)(pa + 8 * APAD);
        uint32_t a2 = *(const uint32_t*)(pa + 8);
        uint32_t a3 = *(const uint32_t*)(pa + 8 * APAD + 8);
#pragma unroll
        for (int nt = 0; nt < 16; nt++) {
            const __half* pb = &sBt[(nt * 8 + fr) * APAD + kt * 16 + fq];
            uint32_t b0 = *(const uint32_t*)pb;
            uint32_t b1 = *(const uint32_t*)(pb + 8);
            mma16816(acc[nt], a0, a1, a2, a3, b0, b1);
        }
    }

    // Epilogue
    int row0 = rowBase + r0 + fr;
    int row1 = row0 + 8;
    bool w0ok = (row0 < nrows), w1ok = (row1 < nrows);
#pragma unroll
    for (int nt = 0; nt < 8; nt++) {          // Ya fp16
        int n = nt * 8 + fq;
        if (w0ok) {
            __half2 v = __floats2half2_rn(acc[nt][0], acc[nt][1]);
            *(__half2*)&Ya[row0 * 64 + n] = v;
        }
        if (w1ok) {
            __half2 v = __floats2half2_rn(acc[nt][2], acc[nt][3]);
            *(__half2*)&Ya[row1 * 64 + n] = v;
        }
    }
#pragma unroll
    for (int nt = 8; nt < 16; nt++) {         // Yb fp32
        int n = (nt - 8) * 8 + fq;
        if (w0ok) *(float2*)&Yb[row0 * 64 + n] = make_float2(acc[nt][0], acc[nt][1]);
        if (w1ok) *(float2*)&Yb[row1 * 64 + n] = make_float2(acc[nt][2], acc[nt][3]);
    }
}

// ---- single: N=64, Y fp16 ----
__global__ void __launch_bounds__(256) mma_single_x2_kernel(
        const float* __restrict__ Xa, const float* __restrict__ Wa_, __half* __restrict__ Ya_,
        const float* __restrict__ Xb, const float* __restrict__ Wb_, __half* __restrict__ Yb_,
        int nrows, int nb) {
    __shared__ __half sA[128 * APAD];    // 18KB
    __shared__ __half sBt[64 * APAD];    // 9KB
    int tid = threadIdx.x;
    int wid = tid >> 5;
    int lane = tid & 31;
    int blk = blockIdx.x;
    const float* X; const float* W; __half* Y;
    int rowBase;
    if (blk < nb) { X = Xa; W = Wa_; Y = Ya_; rowBase = blk * 128; }
    else          { X = Xb; W = Wb_; Y = Yb_; rowBase = (blk - nb) * 128; }

    // A fill
    {
        int r = tid & 127;
        int k0 = (tid >> 7) * 32;
        int grow = rowBase + r;
        uint4* dst = (uint4*)&sA[r * APAD + k0];
#pragma unroll
        for (int j = 0; j < 4; j++) {
            float4 a, b;
            if (grow < nrows) {
                a = ((const float4*)X)[grow * 16 + (k0 >> 2) + 2 * j];
                b = ((const float4*)X)[grow * 16 + (k0 >> 2) + 2 * j + 1];
            } else {
                a = make_float4(0.f, 0.f, 0.f, 0.f);
                b = a;
            }
            dst[j] = f8_to_h8(a, b);
        }
    }
    // Bt fill: thread t -> n = t>>2, k-quarter (t&3)*16
    {
        int n = tid >> 2;
        int k0 = (tid & 3) * 16;
        __half2 tmp[8];
#pragma unroll
        for (int j = 0; j < 8; j++) {
            float w0 = W[(k0 + 2 * j) * 64 + n];
            float w1 = W[(k0 + 2 * j + 1) * 64 + n];
            tmp[j] = __floats2half2_rn(w0, w1);
        }
        uint4* dst = (uint4*)&sBt[n * APAD + k0];
        dst[0] = ((uint4*)tmp)[0];
        dst[1] = ((uint4*)tmp)[1];
    }
    __syncthreads();

    float acc[8][4];
#pragma unroll
    for (int i = 0; i < 8; i++)
#pragma unroll
        for (int j = 0; j < 4; j++) acc[i][j] = 0.f;

    int r0 = wid * 16;
    int fr = lane >> 2;
    int fq = (lane & 3) * 2;
#pragma unroll
    for (int kt = 0; kt < 4; kt++) {
        const __half* pa = &sA[(r0 + fr) * APAD + kt * 16 + fq];
        uint32_t a0 = *(const uint32_t*)pa;
        uint32_t a1 = *(const uint32_t*)(pa + 8 * APAD);
        uint32_t a2 = *(const uint32_t*)(pa + 8);
        uint32_t a3 = *(const uint32_t*)(pa + 8 * APAD + 8);
#pragma unroll
        for (int nt = 0; nt < 8; nt++) {
            const __half* pb = &sBt[(nt * 8 + fr) * APAD + kt * 16 + fq];
            uint32_t b0 = *(const uint32_t*)pb;
            uint32_t b1 = *(const uint32_t*)(pb + 8);
            mma16816(acc[nt], a0, a1, a2, a3, b0, b1);
        }
    }

    int row0 = rowBase + r0 + fr;
    int row1 = row0 + 8;
    bool w0ok = (row0 < nrows), w1ok = (row1 < nrows);
#pragma unroll
    for (int nt = 0; nt < 8; nt++) {
        int n = nt * 8 + fq;
        if (w0ok) {
            __half2 v = __floats2half2_rn(acc[nt][0], acc[nt][1]);
            *(__half2*)&Y[row0 * 64 + n] = v;
        }
        if (w1ok) {
            __half2 v = __floats2half2_rn(acc[nt][2], acc[nt][3]);
            *(__half2*)&Y[row1 * 64 + n] = v;
        }
    }
}

// ---------------- propagation: BOTH stacks per edge, fp16 gathers, unroll-4 ----------------
#define EDGE_FMA_H(e, ua, ub)                                                      \
    {                                                                              \
        float nm = __int_as_float(e.y);                                            \
        float4 va = h4_to_f4(ua);                                                  \
        float4 vb = h4_to_f4(ub);                                                  \
        acca.x = fmaf(nm, va.x, acca.x); acca.y = fmaf(nm, va.y, acca.y);          \
        acca.z = fmaf(nm, va.z, acca.z); acca.w = fmaf(nm, va.w, acca.w);          \
        accb.x = fmaf(nm, vb.x, accb.x); accb.y = fmaf(nm, vb.y, accb.y);          \
        accb.z = fmaf(nm, vb.z, accb.z); accb.w = fmaf(nm, vb.w, accb.w);          \
    }

__global__ void __launch_bounds__(256) prop_both_kernel(
        const __half* __restrict__ Ta, const float* __restrict__ biasa,
        const float* __restrict__ adda, const float* __restrict__ addba,
        float* __restrict__ Houta,
        const __half* __restrict__ Tb, const float* __restrict__ biasb,
        const float* __restrict__ addb, const float* __restrict__ addbb,
        float* __restrict__ Houtb, int relu_add) {
    int lane = threadIdx.x & 31;
    int warp = threadIdx.x >> 5;
    int q = lane & 15;
    int node = (blockIdx.x * 8 + warp) * 2 + (lane >> 4);
    if (node >= N_NODES) return;

    const uint2* Ta8 = (const uint2*)Ta;
    const uint2* Tb8 = (const uint2*)Tb;
    int2 oc = g_offcnt[node];
    int s0 = oc.x, s1 = oc.x + oc.y;
    float4 acca = make_float4(0.f, 0.f, 0.f, 0.f);
    float4 accb = make_float4(0.f, 0.f, 0.f, 0.f);

    int s = s0;
    for (; s + 4 <= s1; s += 4) {
        int2 e0 = g_csredge[s];
        int2 e1 = g_csredge[s + 1];
        int2 e2 = g_csredge[s + 2];
        int2 e3 = g_csredge[s + 3];
        uint2 ua0 = Ta8[e0.x * 16 + q], ub0 = Tb8[e0.x * 16 + q];
        uint2 ua1 = Ta8[e1.x * 16 + q], ub1 = Tb8[e1.x * 16 + q];
        uint2 ua2 = Ta8[e2.x * 16 + q], ub2 = Tb8[e2.x * 16 + q];
        uint2 ua3 = Ta8[e3.x * 16 + q], ub3 = Tb8[e3.x * 16 + q];
        EDGE_FMA_H(e0, ua0, ub0);
        EDGE_FMA_H(e1, ua1, ub1);
        EDGE_FMA_H(e2, ua2, ub2);
        EDGE_FMA_H(e3, ua3, ub3);
    }
    for (; s < s1; s++) {
        int2 e0 = g_csredge[s];
        uint2 ua0 = Ta8[e0.x * 16 + q], ub0 = Tb8[e0.x * 16 + q];
        EDGE_FMA_H(e0, ua0, ub0);
    }

    float dv = g_dinv[node];
    float sn = dv * dv;
    {
        float4 tv = h4_to_f4(Ta8[node * 16 + q]);
        float4 bv = ((const float4*)biasa)[q];
        float4 g;
        g.x = fmaxf(fmaf(sn, tv.x, acca.x) + bv.x, 0.f);
        g.y = fmaxf(fmaf(sn, tv.y, acca.y) + bv.y, 0.f);
        g.z = fmaxf(fmaf(sn, tv.z, acca.z) + bv.z, 0.f);
        g.w = fmaxf(fmaf(sn, tv.w, acca.w) + bv.w, 0.f);
        float4 av = ((const float4*)adda)[node * 16 + q];
        if (relu_add) {
            float4 ab = ((const float4*)addba)[q];
            av.x = fmaxf(av.x + ab.x, 0.f);
            av.y = fmaxf(av.y + ab.y, 0.f);
            av.z = fmaxf(av.z + ab.z, 0.f);
            av.w = fmaxf(av.w + ab.w, 0.f);
        }
        ((float4*)Houta)[node * 16 + q] =
            make_float4(g.x + av.x, g.y + av.y, g.z + av.z, g.w + av.w);
    }
    {
        float4 tv = h4_to_f4(Tb8[node * 16 + q]);
        float4 bv = ((const float4*)biasb)[q];
        float4 g;
        g.x = fmaxf(fmaf(sn, tv.x, accb.x) + bv.x, 0.f);
        g.y = fmaxf(fmaf(sn, tv.y, accb.y) + bv.y, 0.f);
        g.z = fmaxf(fmaf(sn, tv.z, accb.z) + bv.z, 0.f);
        g.w = fmaxf(fmaf(sn, tv.w, accb.w) + bv.w, 0.f);
        float4 av = ((const float4*)addb)[node * 16 + q];
        if (relu_add) {
            float4 ab = ((const float4*)addbb)[q];
            av.x = fmaxf(av.x + ab.x, 0.f);
            av.y = fmaxf(av.y + ab.y, 0.f);
            av.z = fmaxf(av.z + ab.z, 0.f);
            av.w = fmaxf(av.w + ab.w, 0.f);
        }
        ((float4*)Houtb)[node * 16 + q] =
            make_float4(g.x + av.x, g.y + av.y, g.z + av.z, g.w + av.w);
    }
}

// ---------------- mean pool over sorted batch ----------------
__global__ void pool_kernel(const int* __restrict__ batch) {
    int tid = threadIdx.x;
    int c = tid & 63;
    int grp = tid >> 6;
    int base = blockIdx.x * 128;
    float acc = 0.f, cntacc = 0.f;
    int curb = -1;
    for (int j = 0; j < 32; j++) {
        int n = base + grp + j * 4;
        if (n >= N_NODES) break;
        int b = batch[n];
        if (b != curb) {
            if (curb >= 0) {
                atomicAdd(&g_psum[curb * CH + c], acc);
                if (c == 0) atomicAdd(&g_pcnt[curb], cntacc);
            }
            curb = b; acc = 0.f; cntacc = 0.f;
        }
        acc += g_H[n * CH + c] + g_HS[n * CH + c];
        cntacc += 1.0f;
    }
    if (curb >= 0) {
        atomicAdd(&g_psum[curb * CH + c], acc);
        if (c == 0) atomicAdd(&g_pcnt[curb], cntacc);
    }
}

// ---------------- final readout (re-zeroes psum/pcnt) ----------------
__global__ void final_kernel(const float* __restrict__ Wf, const float* __restrict__ bf,
                             float* __restrict__ out) {
    int g = threadIdx.x;
    if (g >= N_GRAPHS) return;
    float inv = 1.0f / fmaxf(g_pcnt[g], 1.0f);
    float s = 0.f;
#pragma unroll
    for (int c = 0; c < CH; c++) {
        s += (g_psum[g * CH + c] * inv) * Wf[c];
        g_psum[g * CH + c] = 0.f;
    }
    g_pcnt[g] = 0.f;
    out[g] = s + bf[0];
}

// ---------------- launch ----------------
extern "C" void kernel_launch(void* const* d_in, const int* in_sizes, int n_in,
                              void* d_out, int out_size) {
    const float* x    = (const float*)d_in[0];
    const float* xsc  = (const float*)d_in[1];
    const float* W1   = (const float*)d_in[2];
    const float* b1   = (const float*)d_in[3];
    const float* W2   = (const float*)d_in[4];
    const float* b2   = (const float*)d_in[5];
    const float* We   = (const float*)d_in[6];
    const float* be   = (const float*)d_in[7];
    const float* W1s  = (const float*)d_in[8];
    const float* b1s  = (const float*)d_in[9];
    const float* W2s  = (const float*)d_in[10];
    const float* b2s  = (const float*)d_in[11];
    const float* Wes  = (const float*)d_in[12];
    const float* bes  = (const float*)d_in[13];
    const float* Wf   = (const float*)d_in[14];
    const float* bf   = (const float*)d_in[15];
    const int*   ei   = (const int*)d_in[16];
    const int*   batch = (const int*)d_in[17];
    float* out = (float*)d_out;

    const int* e_src = ei;
    const int* e_dst = ei + N_EDGES;

    __half *T, *T2;
    float *S, *S2, *H, *HS;
    cudaGetSymbolAddress((void**)&T, g_T);
    cudaGetSymbolAddress((void**)&T2, g_T2);
    cudaGetSymbolAddress((void**)&S, g_S);
    cudaGetSymbolAddress((void**)&S2, g_S2);
    cudaGetSymbolAddress((void**)&H, g_H);
    cudaGetSymbolAddress((void**)&HS, g_HS);

    int e4grid = (N_EDGES / 4 + 255) / 256;
    int nb = (N_NODES + 127) / 128;
    int pgrid = (N_NODES + 15) / 16;

    hist_kernel<<<e4grid, 256>>>(e_dst);
    scan_fused_kernel<<<SCAN_BLOCKS, 256>>>();
    fill_kernel<<<e4grid, 256>>>(e_src, e_dst);

    // layer 1: HMMA dual (T fp16 | S fp32), both stacks
    mma_dual_x2_kernel<<<2 * nb, 256>>>(x, W1, We, T, S,
                                        xsc, W1s, Wes, T2, S2, N_NODES, nb);
    prop_both_kernel<<<pgrid, 256>>>(T, b1, S, be, H,
                                     T2, b1s, S2, bes, HS, 1);
    // layer 2: HMMA single (T fp16)
    mma_single_x2_kernel<<<2 * nb, 256>>>(H, W2, T, HS, W2s, T2, N_NODES, nb);
    prop_both_kernel<<<pgrid, 256>>>(T, b2, H, nullptr, H,
                                     T2, b2s, HS, nullptr, HS, 0);

    pool_kernel<<<(N_NODES + 127) / 128, 256>>>(batch);
    final_kernel<<<1, 64>>>(Wf, bf, out);
}